// round 1
// baseline (speedup 1.0000x reference)
#include <cuda_runtime.h>

// ---------------------------------------------------------------------------
// NeuralMetaLearner fused kernel, fp32 with packed f32x2 FMA (sm_103a).
//
// Per row (B = 1M):
//   h  = LN(x @ W1^T + b1) -> exact GELU          [64]
//   h  = GELU(h @ W2^T + b2)                      [32]
//   g  = h @ Wg^T + bg
//   r  = h @ Wr[regime]^T + br[regime]
//   g2 = (h * sigmoid(emb[regime])) @ Wg^T + bg
//   out = (0.5 g + 0.3 r + 0.2 g2) / clip(exp(log_temp), 0.5, 5)
// ---------------------------------------------------------------------------

#define FMA2(acc, a, b) \
    asm("fma.rn.f32x2 %0, %1, %2, %0;" : "+l"(acc) : "l"(a), "l"(b))

__device__ __forceinline__ unsigned long long pack2(float lo, float hi) {
    unsigned long long r;
    asm("mov.b64 %0, {%1, %2};" : "=l"(r) : "f"(lo), "f"(hi));
    return r;
}
__device__ __forceinline__ float2 unpack2(unsigned long long v) {
    float2 f;
    asm("mov.b64 {%0, %1}, %2;" : "=f"(f.x), "=f"(f.y) : "l"(v));
    return f;
}

constexpr int F  = 128;   // input features
constexpr int H  = 64;    // hidden 1
constexpr int HH = 32;    // hidden 2
constexpr int R  = 4;     // regimes
constexpr int TPB = 128;  // threads per block, 1 row per thread

__global__ __launch_bounds__(TPB)
void nml_fused_kernel(
    const float* __restrict__ x,      // [B, 128]
    const int*   __restrict__ regime, // [B]
    const float* __restrict__ W1,     // [64, 128]
    const float* __restrict__ b1,     // [64]
    const float* __restrict__ gamma,  // [64]
    const float* __restrict__ beta,   // [64]
    const float* __restrict__ W2,     // [32, 64]
    const float* __restrict__ b2,     // [32]
    const float* __restrict__ Wg,     // [2, 32]
    const float* __restrict__ bg,     // [2]
    const float* __restrict__ Wr,     // [4, 2, 32]
    const float* __restrict__ br,     // [4, 2]
    const float* __restrict__ emb,    // [4, 32]
    const float* __restrict__ log_temp, // [1]
    float* __restrict__ out,          // [B, 2]
    int B)
{
    // ---- shared: weights repacked for paired (f32x2) accumulation ----------
    // w1s[k][j2] = (W1[2*j2][k], W1[2*j2+1][k])     k in [0,128), j2 in [0,32)
    // w2s[j][i2] = (W2[2*i2][j], W2[2*i2+1][j])     j in [0,64),  i2 in [0,16)
    __shared__ unsigned long long w1s[F * 32];
    __shared__ unsigned long long w2s[H * 16];
    __shared__ float b1s[H], gms[H], bts[H], b2s[HH];
    __shared__ float wgs[2 * HH], bgs[2], wrs[R * 2 * HH], brs[R * 2];
    __shared__ float sgs[R * HH];   // sigmoid(emb)

    const int tid = threadIdx.x;

    for (int idx = tid; idx < F * 32; idx += TPB) {
        int k = idx >> 5, j2 = idx & 31;
        w1s[idx] = pack2(W1[(2 * j2) * F + k], W1[(2 * j2 + 1) * F + k]);
    }
    for (int idx = tid; idx < H * 16; idx += TPB) {
        int j = idx >> 4, i2 = idx & 15;
        w2s[idx] = pack2(W2[(2 * i2) * H + j], W2[(2 * i2 + 1) * H + j]);
    }
    if (tid < H)      { b1s[tid] = b1[tid]; gms[tid] = gamma[tid]; bts[tid] = beta[tid]; }
    if (tid < HH)     b2s[tid] = b2[tid];
    if (tid < 2 * HH) wgs[tid] = Wg[tid];
    if (tid < 2)      bgs[tid] = bg[tid];
    for (int idx = tid; idx < R * 2 * HH; idx += TPB) wrs[idx] = Wr[idx];
    if (tid < R * 2)  brs[tid] = br[tid];
    for (int idx = tid; idx < R * HH; idx += TPB)
        sgs[idx] = 1.0f / (1.0f + expf(-emb[idx]));
    __syncthreads();

    const int row = blockIdx.x * TPB + tid;
    if (row >= B) return;

    // ---- layer 1: h1 = x @ W1^T  (packed pairs of output channels) --------
    const float4* xr = reinterpret_cast<const float4*>(x + (size_t)row * F);
    unsigned long long acc[32];
#pragma unroll
    for (int j = 0; j < 32; j++) acc[j] = 0ull;

#pragma unroll 2
    for (int kq = 0; kq < F / 4; kq++) {
        float4 xv = xr[kq];
#pragma unroll
        for (int kk = 0; kk < 4; kk++) {
            float xk = (kk == 0) ? xv.x : (kk == 1) ? xv.y : (kk == 2) ? xv.z : xv.w;
            unsigned long long xp = pack2(xk, xk);
            const ulonglong2* wr2 =
                reinterpret_cast<const ulonglong2*>(w1s + (kq * 4 + kk) * 32);
#pragma unroll
            for (int j = 0; j < 16; j++) {
                ulonglong2 w = wr2[j];
                FMA2(acc[2 * j],     xp, w.x);
                FMA2(acc[2 * j + 1], xp, w.y);
            }
        }
    }

    // ---- bias + LayerNorm + exact GELU -------------------------------------
    float h[H];
#pragma unroll
    for (int j = 0; j < 32; j++) {
        float2 v = unpack2(acc[j]);
        h[2 * j]     = v.x + b1s[2 * j];
        h[2 * j + 1] = v.y + b1s[2 * j + 1];
    }
    float mean = 0.0f;
#pragma unroll
    for (int j = 0; j < H; j++) mean += h[j];
    mean *= (1.0f / H);
    float var = 0.0f;
#pragma unroll
    for (int j = 0; j < H; j++) { float d = h[j] - mean; var += d * d; }
    var *= (1.0f / H);
    const float rstd = rsqrtf(var + 1e-5f);
    const float inv_sqrt2 = 0.70710678118654752440f;
#pragma unroll
    for (int j = 0; j < H; j++) {
        float v = gms[j] * (h[j] - mean) * rstd + bts[j];
        h[j] = 0.5f * v * (1.0f + erff(v * inv_sqrt2));
    }

    // ---- layer 2: h2 = GELU(h @ W2^T + b2) ---------------------------------
    unsigned long long a2[16];
#pragma unroll
    for (int i = 0; i < 16; i++) a2[i] = 0ull;

#pragma unroll 4
    for (int j = 0; j < H; j++) {
        unsigned long long hp = pack2(h[j], h[j]);
        const ulonglong2* wr2 = reinterpret_cast<const ulonglong2*>(w2s + j * 16);
#pragma unroll
        for (int i = 0; i < 8; i++) {
            ulonglong2 w = wr2[i];
            FMA2(a2[2 * i],     hp, w.x);
            FMA2(a2[2 * i + 1], hp, w.y);
        }
    }

    float hh[HH];
#pragma unroll
    for (int i = 0; i < 16; i++) {
        float2 v = unpack2(a2[i]);
        float v0 = v.x + b2s[2 * i];
        float v1 = v.y + b2s[2 * i + 1];
        hh[2 * i]     = 0.5f * v0 * (1.0f + erff(v0 * inv_sqrt2));
        hh[2 * i + 1] = 0.5f * v1 * (1.0f + erff(v1 * inv_sqrt2));
    }

    // ---- heads --------------------------------------------------------------
    const int r = regime[row];
    const float* wr0 = wrs + (r * 2) * HH;
    const float* wr1 = wr0 + HH;
    const float* sg  = sgs + r * HH;

    float ga = 0.f, gb = 0.f, ra = 0.f, rb = 0.f, g2a = 0.f, g2b = 0.f;
#pragma unroll
    for (int i = 0; i < HH; i++) {
        float hi  = hh[i];
        float w0  = wgs[i];
        float w1v = wgs[HH + i];
        ga  += hi * w0;
        gb  += hi * w1v;
        float hg = hi * sg[i];
        g2a += hg * w0;
        g2b += hg * w1v;
        ra  += hi * wr0[i];
        rb  += hi * wr1[i];
    }
    ga  += bgs[0]; gb  += bgs[1];
    g2a += bgs[0]; g2b += bgs[1];
    ra  += brs[r * 2]; rb += brs[r * 2 + 1];

    float temp = expf(log_temp[0]);
    temp = fminf(fmaxf(temp, 0.5f), 5.0f);
    const float it = 1.0f / temp;

    float2 o;
    o.x = (0.5f * ga + 0.3f * ra + 0.2f * g2a) * it;
    o.y = (0.5f * gb + 0.3f * rb + 0.2f * g2b) * it;
    reinterpret_cast<float2*>(out)[row] = o;
}

extern "C" void kernel_launch(void* const* d_in, const int* in_sizes, int n_in,
                              void* d_out, int out_size)
{
    const float* x        = (const float*)d_in[0];
    const int*   regime   = (const int*)  d_in[1];
    const float* W1       = (const float*)d_in[2];
    const float* b1       = (const float*)d_in[3];
    const float* gamma    = (const float*)d_in[4];
    const float* beta     = (const float*)d_in[5];
    const float* W2       = (const float*)d_in[6];
    const float* b2       = (const float*)d_in[7];
    const float* Wg       = (const float*)d_in[8];
    const float* bg       = (const float*)d_in[9];
    const float* Wr       = (const float*)d_in[10];
    const float* br       = (const float*)d_in[11];
    const float* emb      = (const float*)d_in[12];
    const float* log_temp = (const float*)d_in[13];
    float* out = (float*)d_out;

    const int B = in_sizes[1];              // regime count == batch
    const int grid = (B + TPB - 1) / TPB;

    nml_fused_kernel<<<grid, TPB>>>(x, regime, W1, b1, gamma, beta, W2, b2,
                                    Wg, bg, Wr, br, emb, log_temp, out, B);
}

// round 2
// speedup vs baseline: 1.1485x; 1.1485x over previous
#include <cuda_runtime.h>

// ---------------------------------------------------------------------------
// NeuralMetaLearner fused kernel — Round 2.
// fp32, packed f32x2 FMA, 2 rows per thread (register blocking) so each
// LDS.128 of W1 feeds 4 FFMA2 instead of 2. Epilogue smem reads vectorized
// to float4. Sequential per-row epilogue bounds register pressure.
// ---------------------------------------------------------------------------

#define FMA2(acc, a, b) \
    asm("fma.rn.f32x2 %0, %1, %2, %0;" : "+l"(acc) : "l"(a), "l"(b))

__device__ __forceinline__ unsigned long long pack2(float lo, float hi) {
    unsigned long long r;
    asm("mov.b64 %0, {%1, %2};" : "=l"(r) : "f"(lo), "f"(hi));
    return r;
}
__device__ __forceinline__ float2 unpack2(unsigned long long v) {
    float2 f;
    asm("mov.b64 {%0, %1}, %2;" : "=f"(f.x), "=f"(f.y) : "l"(v));
    return f;
}

constexpr int F   = 128;   // input features
constexpr int H   = 64;    // hidden 1
constexpr int HH  = 32;    // hidden 2
constexpr int R   = 4;     // regimes
constexpr int TPB = 128;   // threads per block
constexpr int RPT = 2;     // rows per thread
constexpr int ROWS_PER_CTA = TPB * RPT;   // 256

__global__ __launch_bounds__(TPB, 2)
void nml_fused_kernel(
    const float* __restrict__ x,        // [B, 128]
    const int*   __restrict__ regime,   // [B]
    const float* __restrict__ W1,       // [64, 128]
    const float* __restrict__ b1,       // [64]
    const float* __restrict__ gamma,    // [64]
    const float* __restrict__ beta,     // [64]
    const float* __restrict__ W2,       // [32, 64]
    const float* __restrict__ b2,       // [32]
    const float* __restrict__ Wg,       // [2, 32]
    const float* __restrict__ bg,       // [2]
    const float* __restrict__ Wr,       // [4, 2, 32]
    const float* __restrict__ br,       // [4, 2]
    const float* __restrict__ emb,      // [4, 32]
    const float* __restrict__ log_temp, // [1]
    float* __restrict__ out,            // [B, 2]
    int B)
{
    // ---- shared weights, repacked for paired (f32x2) accumulation ----------
    __shared__ __align__(16) unsigned long long w1s[F * 32]; // (k, ch-pair)
    __shared__ __align__(16) unsigned long long w2s[H * 16]; // (j, ch-pair)
    __shared__ __align__(16) float b1s[H], gms[H], bts[H], b2s[HH];
    __shared__ __align__(16) float wgs[2 * HH], wrs[R * 2 * HH], sgs[R * HH];
    __shared__ float bgs[2], brs[R * 2];

    const int tid = threadIdx.x;

    for (int idx = tid; idx < F * 32; idx += TPB) {
        int k = idx >> 5, j2 = idx & 31;
        w1s[idx] = pack2(W1[(2 * j2) * F + k], W1[(2 * j2 + 1) * F + k]);
    }
    for (int idx = tid; idx < H * 16; idx += TPB) {
        int j = idx >> 4, i2 = idx & 15;
        w2s[idx] = pack2(W2[(2 * i2) * H + j], W2[(2 * i2 + 1) * H + j]);
    }
    if (tid < H)      { b1s[tid] = b1[tid]; gms[tid] = gamma[tid]; bts[tid] = beta[tid]; }
    if (tid < HH)     b2s[tid] = b2[tid];
    if (tid < 2 * HH) wgs[tid] = Wg[tid];
    if (tid < 2)      bgs[tid] = bg[tid];
    for (int idx = tid; idx < R * 2 * HH; idx += TPB) wrs[idx] = Wr[idx];
    if (tid < R * 2)  brs[tid] = br[tid];
    for (int idx = tid; idx < R * HH; idx += TPB)
        sgs[idx] = 1.0f / (1.0f + expf(-emb[idx]));
    __syncthreads();

    const int rowA = blockIdx.x * ROWS_PER_CTA + 2 * tid;
    if (rowA >= B) return;
    const bool haveB = (rowA + 1) < B;

    // ---- layer 1 for two rows: each weight LDS feeds 4 FFMA2 ---------------
    const float4* xA = reinterpret_cast<const float4*>(x + (size_t)rowA * F);
    // row B is rowA+1 -> xA + 32 float4

    unsigned long long accA[32], accB[32];
#pragma unroll
    for (int j = 0; j < 32; j++) { accA[j] = 0ull; accB[j] = 0ull; }

#pragma unroll 2
    for (int kq = 0; kq < F / 4; kq++) {
        float4 xa = xA[kq];
        float4 xb = haveB ? xA[kq + 32] : make_float4(0.f, 0.f, 0.f, 0.f);
#pragma unroll
        for (int kk = 0; kk < 4; kk++) {
            float fa = (kk == 0) ? xa.x : (kk == 1) ? xa.y : (kk == 2) ? xa.z : xa.w;
            float fb = (kk == 0) ? xb.x : (kk == 1) ? xb.y : (kk == 2) ? xb.z : xb.w;
            unsigned long long xpA = pack2(fa, fa);
            unsigned long long xpB = pack2(fb, fb);
            const ulonglong2* w =
                reinterpret_cast<const ulonglong2*>(w1s + (kq * 4 + kk) * 32);
#pragma unroll
            for (int j = 0; j < 16; j++) {
                ulonglong2 wv = w[j];
                FMA2(accA[2 * j],     xpA, wv.x);
                FMA2(accA[2 * j + 1], xpA, wv.y);
                FMA2(accB[2 * j],     xpB, wv.x);
                FMA2(accB[2 * j + 1], xpB, wv.y);
            }
        }
    }

    const float inv_sqrt2 = 0.70710678118654752440f;
    float temp = expf(log_temp[0]);
    temp = fminf(fmaxf(temp, 0.5f), 5.0f);
    const float it = 1.0f / temp;

    // ---- per-row epilogue (sequential to bound register pressure) ----------
    auto row_tail = [&](const unsigned long long* acc, int rr) -> float2 {
        float h[H];
#pragma unroll
        for (int j = 0; j < 32; j++) {
            float2 v = unpack2(acc[j]);
            h[2 * j]     = v.x;
            h[2 * j + 1] = v.y;
        }
        const float4* b1v = reinterpret_cast<const float4*>(b1s);
#pragma unroll
        for (int q = 0; q < 16; q++) {
            float4 b = b1v[q];
            h[4 * q]     += b.x;  h[4 * q + 1] += b.y;
            h[4 * q + 2] += b.z;  h[4 * q + 3] += b.w;
        }
        float mean = 0.0f;
#pragma unroll
        for (int j = 0; j < H; j++) mean += h[j];
        mean *= (1.0f / H);
        float var = 0.0f;
#pragma unroll
        for (int j = 0; j < H; j++) { float d = h[j] - mean; var += d * d; }
        var *= (1.0f / H);
        const float rstd = rsqrtf(var + 1e-5f);

        const float4* gv = reinterpret_cast<const float4*>(gms);
        const float4* bv = reinterpret_cast<const float4*>(bts);
#pragma unroll
        for (int q = 0; q < 16; q++) {
            float4 g = gv[q], be = bv[q];
            float v0 = g.x * (h[4 * q]     - mean) * rstd + be.x;
            float v1 = g.y * (h[4 * q + 1] - mean) * rstd + be.y;
            float v2 = g.z * (h[4 * q + 2] - mean) * rstd + be.z;
            float v3 = g.w * (h[4 * q + 3] - mean) * rstd + be.w;
            h[4 * q]     = 0.5f * v0 * (1.0f + erff(v0 * inv_sqrt2));
            h[4 * q + 1] = 0.5f * v1 * (1.0f + erff(v1 * inv_sqrt2));
            h[4 * q + 2] = 0.5f * v2 * (1.0f + erff(v2 * inv_sqrt2));
            h[4 * q + 3] = 0.5f * v3 * (1.0f + erff(v3 * inv_sqrt2));
        }

        // layer 2
        unsigned long long a2[16];
#pragma unroll
        for (int i = 0; i < 16; i++) a2[i] = 0ull;
#pragma unroll 4
        for (int j = 0; j < H; j++) {
            unsigned long long hp = pack2(h[j], h[j]);
            const ulonglong2* w = reinterpret_cast<const ulonglong2*>(w2s + j * 16);
#pragma unroll
            for (int i = 0; i < 8; i++) {
                ulonglong2 wv = w[i];
                FMA2(a2[2 * i],     hp, wv.x);
                FMA2(a2[2 * i + 1], hp, wv.y);
            }
        }

        float hh[HH];
        const float4* b2v = reinterpret_cast<const float4*>(b2s);
#pragma unroll
        for (int q = 0; q < 8; q++) {
            float2 v0 = unpack2(a2[2 * q]);
            float2 v1 = unpack2(a2[2 * q + 1]);
            float4 b = b2v[q];
            float u0 = v0.x + b.x, u1 = v0.y + b.y, u2 = v1.x + b.z, u3 = v1.y + b.w;
            hh[4 * q]     = 0.5f * u0 * (1.0f + erff(u0 * inv_sqrt2));
            hh[4 * q + 1] = 0.5f * u1 * (1.0f + erff(u1 * inv_sqrt2));
            hh[4 * q + 2] = 0.5f * u2 * (1.0f + erff(u2 * inv_sqrt2));
            hh[4 * q + 3] = 0.5f * u3 * (1.0f + erff(u3 * inv_sqrt2));
        }

        // heads (vectorized smem reads)
        const float4* wg0 = reinterpret_cast<const float4*>(wgs);
        const float4* wg1 = reinterpret_cast<const float4*>(wgs + HH);
        const float4* sgp = reinterpret_cast<const float4*>(sgs + rr * HH);
        const float4* w0p = reinterpret_cast<const float4*>(wrs + rr * 2 * HH);
        const float4* w1p = reinterpret_cast<const float4*>(wrs + rr * 2 * HH + HH);

        float ga = 0.f, gb = 0.f, ra = 0.f, rb = 0.f, g2a = 0.f, g2b = 0.f;
#pragma unroll
        for (int q = 0; q < 8; q++) {
            float4 a = wg0[q], b = wg1[q], s = sgp[q], c = w0p[q], d = w1p[q];
            float h0 = hh[4 * q], h1 = hh[4 * q + 1], h2 = hh[4 * q + 2], h3 = hh[4 * q + 3];
            ga  += h0 * a.x + h1 * a.y + h2 * a.z + h3 * a.w;
            gb  += h0 * b.x + h1 * b.y + h2 * b.z + h3 * b.w;
            ra  += h0 * c.x + h1 * c.y + h2 * c.z + h3 * c.w;
            rb  += h0 * d.x + h1 * d.y + h2 * d.z + h3 * d.w;
            float e0 = h0 * s.x, e1 = h1 * s.y, e2 = h2 * s.z, e3 = h3 * s.w;
            g2a += e0 * a.x + e1 * a.y + e2 * a.z + e3 * a.w;
            g2b += e0 * b.x + e1 * b.y + e2 * b.z + e3 * b.w;
        }
        ga  += bgs[0]; gb  += bgs[1];
        g2a += bgs[0]; g2b += bgs[1];
        ra  += brs[rr * 2]; rb += brs[rr * 2 + 1];

        float2 o;
        o.x = (0.5f * ga + 0.3f * ra + 0.2f * g2a) * it;
        o.y = (0.5f * gb + 0.3f * rb + 0.2f * g2b) * it;
        return o;
    };

    if (haveB) {
        const int2 rg = *reinterpret_cast<const int2*>(regime + rowA);
        float2 oA = row_tail(accA, rg.x);
        float2 oB = row_tail(accB, rg.y);
        float4 o4 = make_float4(oA.x, oA.y, oB.x, oB.y);
        reinterpret_cast<float4*>(out)[rowA >> 1] = o4;
    } else {
        const int rA = regime[rowA];
        float2 oA = row_tail(accA, rA);
        reinterpret_cast<float2*>(out)[rowA] = oA;
    }
}

extern "C" void kernel_launch(void* const* d_in, const int* in_sizes, int n_in,
                              void* d_out, int out_size)
{
    const float* x        = (const float*)d_in[0];
    const int*   regime   = (const int*)  d_in[1];
    const float* W1       = (const float*)d_in[2];
    const float* b1       = (const float*)d_in[3];
    const float* gamma    = (const float*)d_in[4];
    const float* beta     = (const float*)d_in[5];
    const float* W2       = (const float*)d_in[6];
    const float* b2       = (const float*)d_in[7];
    const float* Wg       = (const float*)d_in[8];
    const float* bg       = (const float*)d_in[9];
    const float* Wr       = (const float*)d_in[10];
    const float* br       = (const float*)d_in[11];
    const float* emb      = (const float*)d_in[12];
    const float* log_temp = (const float*)d_in[13];
    float* out = (float*)d_out;

    const int B = in_sizes[1];
    const int grid = (B + ROWS_PER_CTA - 1) / ROWS_PER_CTA;

    nml_fused_kernel<<<grid, TPB>>>(x, regime, W1, b1, gamma, beta, W2, b2,
                                    Wg, bg, Wr, br, emb, log_temp, out, B);
}

// round 4
// speedup vs baseline: 2.5572x; 2.2265x over previous
#include <cuda_runtime.h>
#include <cuda_bf16.h>
#include <cstdint>

// ---------------------------------------------------------------------------
// Round 4: warp-level HMMA (mma.sync m16n8k16 bf16) with split-bf16 fp32
// emulation (hi*hi + hi*lo + lo*hi), fused LN/GELU/heads epilogue in
// registers. 256 threads/CTA, 32 rows/warp, 256 rows/CTA.
// ---------------------------------------------------------------------------

constexpr int TPB  = 256;
constexpr int ROWS = 256;

// smem layout (32-bit word offsets)
constexpr int B1F = 0;       // W1 B-frags: word = (hl*64 + kpg)*72 + n   (9216 w)
constexpr int B2F = 9216;    // W2 B-frags: word = (hl*32 + kpg)*40 + n   (2560 w)
constexpr int PAR = 11776;   // float params (736 w)
constexpr int P_B1 = 0, P_GM = 64, P_BT = 128, P_B2 = 192, P_WG = 224,
              P_BG = 288, P_BR = 290, P_SG = 304, P_WR = 448; // end 736
constexpr int SMEM_BYTES = (11776 + 736) * 4;   // 50048

static __device__ __forceinline__ void mma_bf16(float d[4], const uint32_t a[4],
                                                uint32_t b0, uint32_t b1) {
    asm volatile(
        "mma.sync.aligned.m16n8k16.row.col.f32.bf16.bf16.f32 "
        "{%0,%1,%2,%3}, {%4,%5,%6,%7}, {%8,%9}, {%0,%1,%2,%3};"
        : "+f"(d[0]), "+f"(d[1]), "+f"(d[2]), "+f"(d[3])
        : "r"(a[0]), "r"(a[1]), "r"(a[2]), "r"(a[3]), "r"(b0), "r"(b1));
}

struct Split { uint32_t hi, lo; };
static __device__ __forceinline__ Split split2(float a, float b) {
    __nv_bfloat162 h = __floats2bfloat162_rn(a, b);
    float2 hf = __bfloat1622float2(h);
    __nv_bfloat162 l = __floats2bfloat162_rn(a - hf.x, b - hf.y);
    Split s;
    s.hi = *reinterpret_cast<uint32_t*>(&h);
    s.lo = *reinterpret_cast<uint32_t*>(&l);
    return s;
}

static __device__ __forceinline__ float gelu(float v) {
    return 0.5f * v * (1.0f + erff(v * 0.70710678118654752440f));
}

__global__ __launch_bounds__(TPB)
void nml_mma_kernel(
    const float* __restrict__ x, const int* __restrict__ regime,
    const float* __restrict__ W1, const float* __restrict__ b1,
    const float* __restrict__ gamma, const float* __restrict__ beta,
    const float* __restrict__ W2, const float* __restrict__ b2,
    const float* __restrict__ Wg, const float* __restrict__ bg,
    const float* __restrict__ Wr, const float* __restrict__ br,
    const float* __restrict__ emb, const float* __restrict__ log_temp,
    float* __restrict__ out, int B)
{
    extern __shared__ float smem[];
    uint32_t* smu = reinterpret_cast<uint32_t*>(smem);
    float* par = smem + PAR;

    const int tid = threadIdx.x;

    // ---- W1 -> split-bf16 B fragments --------------------------------------
    // word(hl, kpg, n) = B1F + (hl*64 + kpg)*72 + n ; value = (W1[n][2kpg], W1[n][2kpg+1])
#pragma unroll
    for (int it = 0; it < 4096 / TPB; it++) {
        int i = it * TPB + tid;
        int n = i >> 6, kpg = i & 63;
        float2 wv = *reinterpret_cast<const float2*>(W1 + n * 128 + kpg * 2);
        Split s = split2(wv.x, wv.y);
        smu[B1F + kpg * 72 + n]        = s.hi;
        smu[B1F + (64 + kpg) * 72 + n] = s.lo;
    }
    // ---- W2 -----------------------------------------------------------------
#pragma unroll
    for (int it = 0; it < 1024 / TPB; it++) {
        int i = it * TPB + tid;
        int n = i >> 5, kpg = i & 31;
        float2 wv = *reinterpret_cast<const float2*>(W2 + n * 64 + kpg * 2);
        Split s = split2(wv.x, wv.y);
        smu[B2F + kpg * 40 + n]        = s.hi;
        smu[B2F + (32 + kpg) * 40 + n] = s.lo;
    }
    // ---- params -------------------------------------------------------------
    if (tid < 64) {
        par[P_B1 + tid] = b1[tid];
        par[P_GM + tid] = gamma[tid];
        par[P_BT + tid] = beta[tid];
        par[P_WG + tid] = Wg[tid];
    }
    if (tid < 32) par[P_B2 + tid] = b2[tid];
    if (tid < 2)  par[P_BG + tid] = bg[tid];
    if (tid < 8)  par[P_BR + tid] = br[tid];
    if (tid < 128) {
        int rr = tid >> 5, c = tid & 31;
        par[P_SG + rr * 36 + c] = 1.0f / (1.0f + expf(-emb[tid]));
    }
    {
        int rr = tid >> 6, hh = (tid >> 5) & 1, c = tid & 31;
        par[P_WR + rr * 72 + hh * 36 + c] = Wr[tid];
    }
    __syncthreads();

    const int wid  = tid >> 5;
    const int lane = tid & 31;
    const int q    = lane >> 2;     // 0..7
    const int s4   = lane & 3;      // 0..3
    const long warpRow = (long)blockIdx.x * ROWS + wid * 32;
    const long Bm1 = B - 1;

    // ======================= layer 1: D1 = X @ W1^T =========================
    float d1[2][8][4];
#pragma unroll
    for (int t = 0; t < 2; t++)
#pragma unroll
        for (int nt = 0; nt < 8; nt++)
#pragma unroll
            for (int j = 0; j < 4; j++) d1[t][nt][j] = 0.f;

#pragma unroll
    for (int ks = 0; ks < 8; ks++) {
        uint32_t Ahi[2][4], Alo[2][4];
#pragma unroll
        for (int t = 0; t < 2; t++) {
            long rlo = warpRow + t * 16 + q;
            long rhi = rlo + 8;
            if (rlo > Bm1) rlo = Bm1;
            if (rhi > Bm1) rhi = Bm1;
            const float* plo = x + rlo * 128 + s4 * 2 + ks * 16;
            const float* phi = x + rhi * 128 + s4 * 2 + ks * 16;
            float2 p0 = *reinterpret_cast<const float2*>(plo);
            float2 p2 = *reinterpret_cast<const float2*>(plo + 8);
            float2 p1 = *reinterpret_cast<const float2*>(phi);
            float2 p3 = *reinterpret_cast<const float2*>(phi + 8);
            Split s0 = split2(p0.x, p0.y);
            Split s1 = split2(p1.x, p1.y);
            Split s2 = split2(p2.x, p2.y);
            Split s3 = split2(p3.x, p3.y);
            Ahi[t][0] = s0.hi; Alo[t][0] = s0.lo;
            Ahi[t][1] = s1.hi; Alo[t][1] = s1.lo;
            Ahi[t][2] = s2.hi; Alo[t][2] = s2.lo;
            Ahi[t][3] = s3.hi; Alo[t][3] = s3.lo;
        }
#pragma unroll
        for (int nt = 0; nt < 8; nt++) {
            int n = nt * 8 + q;
            uint32_t bh0 = smu[B1F + (ks * 8 + s4) * 72 + n];
            uint32_t bh1 = smu[B1F + (ks * 8 + s4 + 4) * 72 + n];
            uint32_t bl0 = smu[B1F + (64 + ks * 8 + s4) * 72 + n];
            uint32_t bl1 = smu[B1F + (64 + ks * 8 + s4 + 4) * 72 + n];
#pragma unroll
            for (int t = 0; t < 2; t++) {
                mma_bf16(d1[t][nt], Ahi[t], bh0, bh1);
                mma_bf16(d1[t][nt], Ahi[t], bl0, bl1);
                mma_bf16(d1[t][nt], Alo[t], bh0, bh1);
            }
        }
    }

    // ============ bias + LayerNorm + GELU -> layer-2 A fragments ============
    uint32_t A2h[2][4][4], A2l[2][4][4];
#pragma unroll
    for (int t = 0; t < 2; t++) {
        // bias
#pragma unroll
        for (int nt = 0; nt < 8; nt++) {
            float2 bp = *reinterpret_cast<const float2*>(par + P_B1 + nt * 8 + s4 * 2);
            d1[t][nt][0] += bp.x; d1[t][nt][1] += bp.y;
            d1[t][nt][2] += bp.x; d1[t][nt][3] += bp.y;
        }
        // mean (rows r and r+8 separately)
        float slo = 0.f, shi = 0.f;
#pragma unroll
        for (int nt = 0; nt < 8; nt++) {
            slo += d1[t][nt][0] + d1[t][nt][1];
            shi += d1[t][nt][2] + d1[t][nt][3];
        }
        slo += __shfl_xor_sync(0xffffffffu, slo, 1);
        slo += __shfl_xor_sync(0xffffffffu, slo, 2);
        shi += __shfl_xor_sync(0xffffffffu, shi, 1);
        shi += __shfl_xor_sync(0xffffffffu, shi, 2);
        float mulo = slo * (1.0f / 64.0f);
        float muhi = shi * (1.0f / 64.0f);
        // variance
        float vlo = 0.f, vhi = 0.f;
#pragma unroll
        for (int nt = 0; nt < 8; nt++) {
            float a0 = d1[t][nt][0] - mulo, a1 = d1[t][nt][1] - mulo;
            float a2 = d1[t][nt][2] - muhi, a3 = d1[t][nt][3] - muhi;
            vlo += a0 * a0 + a1 * a1;
            vhi += a2 * a2 + a3 * a3;
        }
        vlo += __shfl_xor_sync(0xffffffffu, vlo, 1);
        vlo += __shfl_xor_sync(0xffffffffu, vlo, 2);
        vhi += __shfl_xor_sync(0xffffffffu, vhi, 1);
        vhi += __shfl_xor_sync(0xffffffffu, vhi, 2);
        float rstdlo = rsqrtf(vlo * (1.0f / 64.0f) + 1e-5f);
        float rstdhi = rsqrtf(vhi * (1.0f / 64.0f) + 1e-5f);
        // gamma/beta + GELU
        float g[8][4];
#pragma unroll
        for (int nt = 0; nt < 8; nt++) {
            float2 gm = *reinterpret_cast<const float2*>(par + P_GM + nt * 8 + s4 * 2);
            float2 bt = *reinterpret_cast<const float2*>(par + P_BT + nt * 8 + s4 * 2);
            g[nt][0] = gelu(gm.x * (d1[t][nt][0] - mulo) * rstdlo + bt.x);
            g[nt][1] = gelu(gm.y * (d1[t][nt][1] - mulo) * rstdlo + bt.y);
            g[nt][2] = gelu(gm.x * (d1[t][nt][2] - muhi) * rstdhi + bt.x);
            g[nt][3] = gelu(gm.y * (d1[t][nt][3] - muhi) * rstdhi + bt.y);
        }
        // pack layer-2 A fragments (D layout == A layout)
#pragma unroll
        for (int k2 = 0; k2 < 4; k2++) {
            Split s0 = split2(g[2 * k2][0],     g[2 * k2][1]);
            Split s1 = split2(g[2 * k2][2],     g[2 * k2][3]);
            Split s2 = split2(g[2 * k2 + 1][0], g[2 * k2 + 1][1]);
            Split s3 = split2(g[2 * k2 + 1][2], g[2 * k2 + 1][3]);
            A2h[t][k2][0] = s0.hi; A2l[t][k2][0] = s0.lo;
            A2h[t][k2][1] = s1.hi; A2l[t][k2][1] = s1.lo;
            A2h[t][k2][2] = s2.hi; A2l[t][k2][2] = s2.lo;
            A2h[t][k2][3] = s3.hi; A2l[t][k2][3] = s3.lo;
        }
    }

    // ======================= layer 2: D2 = H @ W2^T =========================
    float d2[2][4][4];
#pragma unroll
    for (int t = 0; t < 2; t++)
#pragma unroll
        for (int nt = 0; nt < 4; nt++)
#pragma unroll
            for (int j = 0; j < 4; j++) d2[t][nt][j] = 0.f;

#pragma unroll
    for (int k2 = 0; k2 < 4; k2++) {
#pragma unroll
        for (int nt = 0; nt < 4; nt++) {
            int n = nt * 8 + q;
            uint32_t bh0 = smu[B2F + (k2 * 8 + s4) * 40 + n];
            uint32_t bh1 = smu[B2F + (k2 * 8 + s4 + 4) * 40 + n];
            uint32_t bl0 = smu[B2F + (32 + k2 * 8 + s4) * 40 + n];
            uint32_t bl1 = smu[B2F + (32 + k2 * 8 + s4 + 4) * 40 + n];
#pragma unroll
            for (int t = 0; t < 2; t++) {
                mma_bf16(d2[t][nt], A2h[t][k2], bh0, bh1);
                mma_bf16(d2[t][nt], A2h[t][k2], bl0, bl1);
                mma_bf16(d2[t][nt], A2l[t][k2], bh0, bh1);
            }
        }
    }

    // ======================= bias + GELU + heads ============================
    float temp = expf(log_temp[0]);
    temp = fminf(fmaxf(temp, 0.5f), 5.0f);
    const float it = 1.0f / temp;
    const float bg0 = par[P_BG], bg1 = par[P_BG + 1];

#pragma unroll
    for (int t = 0; t < 2; t++) {
        long growlo = warpRow + t * 16 + q;
        long growhi = growlo + 8;
        int rrlo = regime[growlo > Bm1 ? Bm1 : growlo];
        int rrhi = regime[growhi > Bm1 ? Bm1 : growhi];

        float hh[4][4];
#pragma unroll
        for (int nt = 0; nt < 4; nt++) {
            float2 bp = *reinterpret_cast<const float2*>(par + P_B2 + nt * 8 + s4 * 2);
            hh[nt][0] = gelu(d2[t][nt][0] + bp.x);
            hh[nt][1] = gelu(d2[t][nt][1] + bp.y);
            hh[nt][2] = gelu(d2[t][nt][2] + bp.x);
            hh[nt][3] = gelu(d2[t][nt][3] + bp.y);
        }

        float galo = 0.f, gblo = 0.f, ralo = 0.f, rblo = 0.f, g2alo = 0.f, g2blo = 0.f;
        float gahi = 0.f, gbhi = 0.f, rahi = 0.f, rbhi = 0.f, g2ahi = 0.f, g2bhi = 0.f;
#pragma unroll
        for (int nt = 0; nt < 4; nt++) {
            int c = nt * 8 + s4 * 2;
            float2 w0 = *reinterpret_cast<const float2*>(par + P_WG + c);
            float2 w1 = *reinterpret_cast<const float2*>(par + P_WG + 32 + c);
            float2 sl = *reinterpret_cast<const float2*>(par + P_SG + rrlo * 36 + c);
            float2 sh = *reinterpret_cast<const float2*>(par + P_SG + rrhi * 36 + c);
            float2 rl0 = *reinterpret_cast<const float2*>(par + P_WR + rrlo * 72 + c);
            float2 rl1 = *reinterpret_cast<const float2*>(par + P_WR + rrlo * 72 + 36 + c);
            float2 rh0 = *reinterpret_cast<const float2*>(par + P_WR + rrhi * 72 + c);
            float2 rh1 = *reinterpret_cast<const float2*>(par + P_WR + rrhi * 72 + 36 + c);

            float h0 = hh[nt][0], h1 = hh[nt][1], h2 = hh[nt][2], h3 = hh[nt][3];
            galo += h0 * w0.x + h1 * w0.y;   gblo += h0 * w1.x + h1 * w1.y;
            gahi += h2 * w0.x + h3 * w0.y;   gbhi += h2 * w1.x + h3 * w1.y;
            ralo += h0 * rl0.x + h1 * rl0.y; rblo += h0 * rl1.x + h1 * rl1.y;
            rahi += h2 * rh0.x + h3 * rh0.y; rbhi += h2 * rh1.x + h3 * rh1.y;
            float e0 = h0 * sl.x, e1 = h1 * sl.y;
            float e2 = h2 * sh.x, e3 = h3 * sh.y;
            g2alo += e0 * w0.x + e1 * w0.y;  g2blo += e0 * w1.x + e1 * w1.y;
            g2ahi += e2 * w0.x + e3 * w0.y;  g2bhi += e2 * w1.x + e3 * w1.y;
        }
#pragma unroll
        for (int d = 1; d <= 2; d <<= 1) {
            galo += __shfl_xor_sync(0xffffffffu, galo, d);
            gblo += __shfl_xor_sync(0xffffffffu, gblo, d);
            ralo += __shfl_xor_sync(0xffffffffu, ralo, d);
            rblo += __shfl_xor_sync(0xffffffffu, rblo, d);
            g2alo += __shfl_xor_sync(0xffffffffu, g2alo, d);
            g2blo += __shfl_xor_sync(0xffffffffu, g2blo, d);
            gahi += __shfl_xor_sync(0xffffffffu, gahi, d);
            gbhi += __shfl_xor_sync(0xffffffffu, gbhi, d);
            rahi += __shfl_xor_sync(0xffffffffu, rahi, d);
            rbhi += __shfl_xor_sync(0xffffffffu, rbhi, d);
            g2ahi += __shfl_xor_sync(0xffffffffu, g2ahi, d);
            g2bhi += __shfl_xor_sync(0xffffffffu, g2bhi, d);
        }

        if (s4 == 0) {
            if (growlo < B) {
                float2 o;
                o.x = (0.5f * (galo + bg0) + 0.3f * (ralo + par[P_BR + rrlo * 2]) +
                       0.2f * (g2alo + bg0)) * it;
                o.y = (0.5f * (gblo + bg1) + 0.3f * (rblo + par[P_BR + rrlo * 2 + 1]) +
                       0.2f * (g2blo + bg1)) * it;
                reinterpret_cast<float2*>(out)[growlo] = o;
            }
            if (growhi < B) {
                float2 o;
                o.x = (0.5f * (gahi + bg0) + 0.3f * (rahi + par[P_BR + rrhi * 2]) +
                       0.2f * (g2ahi + bg0)) * it;
                o.y = (0.5f * (gbhi + bg1) + 0.3f * (rbhi + par[P_BR + rrhi * 2 + 1]) +
                       0.2f * (g2bhi + bg1)) * it;
                reinterpret_cast<float2*>(out)[growhi] = o;
            }
        }
    }
}

extern "C" void kernel_launch(void* const* d_in, const int* in_sizes, int n_in,
                              void* d_out, int out_size)
{
    const float* x        = (const float*)d_in[0];
    const int*   regime   = (const int*)  d_in[1];
    const float* W1       = (const float*)d_in[2];
    const float* b1       = (const float*)d_in[3];
    const float* gamma    = (const float*)d_in[4];
    const float* beta     = (const float*)d_in[5];
    const float* W2       = (const float*)d_in[6];
    const float* b2       = (const float*)d_in[7];
    const float* Wg       = (const float*)d_in[8];
    const float* bg       = (const float*)d_in[9];
    const float* Wr       = (const float*)d_in[10];
    const float* br       = (const float*)d_in[11];
    const float* emb      = (const float*)d_in[12];
    const float* log_temp = (const float*)d_in[13];
    float* out = (float*)d_out;

    const int B = in_sizes[1];
    const int grid = (B + ROWS - 1) / ROWS;

    cudaFuncSetAttribute(nml_mma_kernel,
                         cudaFuncAttributeMaxDynamicSharedMemorySize, SMEM_BYTES);
    nml_mma_kernel<<<grid, TPB, SMEM_BYTES>>>(x, regime, W1, b1, gamma, beta,
                                              W2, b2, Wg, bg, Wr, br, emb,
                                              log_temp, out, B);
}

// round 5
// speedup vs baseline: 3.2641x; 1.2764x over previous
#include <cuda_runtime.h>
#include <cuda_bf16.h>
#include <cstdint>

// ---------------------------------------------------------------------------
// Round 5: split-bf16 HMMA (mma.sync m16n8k16) as R4, plus:
//  - 2 CTAs/SM (launch_bounds cap 128 regs, per-tile epilogue to fit)
//  - LDS.64 B-fragment layout (conflict-free, stride 72/40 words)
//  - branchless A&S erf GELU (RCP+EX2), cheap bf16 split/decode
// ---------------------------------------------------------------------------

constexpr int TPB  = 256;
constexpr int ROWS = 256;

// smem word offsets
constexpr int B1F = 0;       // W1 frags: word = ((hl*32 + ks*4 + s4)*72 + n)*2 + j
constexpr int B2F = 9216;    // W2 frags: word = ((hl*16 + k2*4 + s4)*40 + n)*2 + j
constexpr int PAR = 11776;   // float params
constexpr int P_B1 = 0, P_GM = 64, P_BT = 128, P_B2 = 192, P_WG = 224,
              P_BG = 288, P_BR = 290, P_SG = 304, P_WR = 448; // end 736
constexpr int SMEM_BYTES = (11776 + 736) * 4;

static __device__ __forceinline__ void mma_bf16(float d[4], const uint32_t a[4],
                                                uint32_t b0, uint32_t b1) {
    asm volatile(
        "mma.sync.aligned.m16n8k16.row.col.f32.bf16.bf16.f32 "
        "{%0,%1,%2,%3}, {%4,%5,%6,%7}, {%8,%9}, {%0,%1,%2,%3};"
        : "+f"(d[0]), "+f"(d[1]), "+f"(d[2]), "+f"(d[3])
        : "r"(a[0]), "r"(a[1]), "r"(a[2]), "r"(a[3]), "r"(b0), "r"(b1));
}

struct Split { uint32_t hi, lo; };
// pack (a,b) -> bf16x2 hi + bf16x2 residual lo.  low half = a, high half = b.
static __device__ __forceinline__ Split split2(float a, float b) {
    Split s;
    asm("cvt.rn.bf16x2.f32 %0, %1, %2;" : "=r"(s.hi) : "f"(b), "f"(a));
    float ha = __uint_as_float(s.hi << 16);
    float hb = __uint_as_float(s.hi & 0xFFFF0000u);
    asm("cvt.rn.bf16x2.f32 %0, %1, %2;" : "=r"(s.lo) : "f"(b - hb), "f"(a - ha));
    return s;
}

static __device__ __forceinline__ float rcp_fast(float x) {
    float r; asm("rcp.approx.f32 %0, %1;" : "=f"(r) : "f"(x)); return r;
}
static __device__ __forceinline__ float ex2_fast(float x) {
    float r; asm("ex2.approx.f32 %0, %1;" : "=f"(r) : "f"(x)); return r;
}
// exact-erf GELU via Abramowitz-Stegun 7.1.26 (|erf err| <= 1.5e-7), branchless
static __device__ __forceinline__ float gelu(float v) {
    float x = fabsf(v) * 0.70710678118654752440f;   // |v|/sqrt(2)
    float t = rcp_fast(fmaf(0.3275911f, x, 1.0f));
    float p = fmaf(1.061405429f, t, -1.453152027f);
    p = fmaf(p, t, 1.421413741f);
    p = fmaf(p, t, -0.284496736f);
    p = fmaf(p, t, 0.254829592f);
    p = p * t;
    float e = ex2_fast(x * x * -1.4426950408889634f);  // exp(-x^2)
    float erf_ = 1.0f - p * e;                          // erf(x), x >= 0
    // gelu = 0.5*v + 0.5*|v|*erf(|v|/sqrt2)*sign-fold = 0.5*v + 0.5*|v|*erf_
    return fmaf(0.5f * fabsf(v), erf_, 0.5f * v);
}

__global__ __launch_bounds__(TPB, 2)
void nml_mma_kernel(
    const float* __restrict__ x, const int* __restrict__ regime,
    const float* __restrict__ W1, const float* __restrict__ b1,
    const float* __restrict__ gamma, const float* __restrict__ beta,
    const float* __restrict__ W2, const float* __restrict__ b2,
    const float* __restrict__ Wg, const float* __restrict__ bg,
    const float* __restrict__ Wr, const float* __restrict__ br,
    const float* __restrict__ emb, const float* __restrict__ log_temp,
    float* __restrict__ out, int B)
{
    extern __shared__ float smem[];
    uint32_t* smu = reinterpret_cast<uint32_t*>(smem);
    float* par = smem + PAR;

    const int tid = threadIdx.x;

    // ---- W1 -> split-bf16 B fragments (paired layout for LDS.64) -----------
#pragma unroll
    for (int it = 0; it < 4096 / TPB; it++) {
        int i = it * TPB + tid;
        int n = i >> 6, kpg = i & 63;
        int ks = kpg >> 3, r = kpg & 7, sq = r & 3, j = r >> 2;
        float2 wv = *reinterpret_cast<const float2*>(W1 + n * 128 + kpg * 2);
        Split s = split2(wv.x, wv.y);
        smu[B1F + ((ks * 4 + sq) * 72 + n) * 2 + j]        = s.hi;
        smu[B1F + (((32 + ks * 4 + sq)) * 72 + n) * 2 + j] = s.lo;
    }
    // ---- W2 -----------------------------------------------------------------
#pragma unroll
    for (int it = 0; it < 1024 / TPB; it++) {
        int i = it * TPB + tid;
        int n = i >> 5, kpg = i & 31;
        int k2 = kpg >> 3, r = kpg & 7, sq = r & 3, j = r >> 2;
        float2 wv = *reinterpret_cast<const float2*>(W2 + n * 64 + kpg * 2);
        Split s = split2(wv.x, wv.y);
        smu[B2F + ((k2 * 4 + sq) * 40 + n) * 2 + j]        = s.hi;
        smu[B2F + ((16 + k2 * 4 + sq) * 40 + n) * 2 + j]   = s.lo;
    }
    // ---- params -------------------------------------------------------------
    if (tid < 64) {
        par[P_B1 + tid] = b1[tid];
        par[P_GM + tid] = gamma[tid];
        par[P_BT + tid] = beta[tid];
        par[P_WG + tid] = Wg[tid];
    }
    if (tid < 32) par[P_B2 + tid] = b2[tid];
    if (tid < 2)  par[P_BG + tid] = bg[tid];
    if (tid < 8)  par[P_BR + tid] = br[tid];
    if (tid < 128) {
        int rr = tid >> 5, c = tid & 31;
        par[P_SG + rr * 36 + c] = 1.0f / (1.0f + expf(-emb[tid]));
    }
    {
        int rr = tid >> 6, hf = (tid >> 5) & 1, c = tid & 31;
        par[P_WR + rr * 72 + hf * 36 + c] = Wr[tid];
    }
    __syncthreads();

    const int wid  = tid >> 5;
    const int lane = tid & 31;
    const int q    = lane >> 2;     // 0..7
    const int s4   = lane & 3;      // 0..3
    const long warpRow = (long)blockIdx.x * ROWS + wid * 32;
    const long Bm1 = B - 1;

    // ======================= layer 1: D1 = X @ W1^T =========================
    float d1[2][8][4];
#pragma unroll
    for (int t = 0; t < 2; t++)
#pragma unroll
        for (int nt = 0; nt < 8; nt++)
#pragma unroll
            for (int j = 0; j < 4; j++) d1[t][nt][j] = 0.f;

#pragma unroll 2
    for (int ks = 0; ks < 8; ks++) {
        uint32_t Ahi[2][4], Alo[2][4];
#pragma unroll
        for (int t = 0; t < 2; t++) {
            long rlo = warpRow + t * 16 + q;
            long rhi = rlo + 8;
            if (rlo > Bm1) rlo = Bm1;
            if (rhi > Bm1) rhi = Bm1;
            const float* plo = x + rlo * 128 + s4 * 2 + ks * 16;
            const float* phi = x + rhi * 128 + s4 * 2 + ks * 16;
            float2 p0 = *reinterpret_cast<const float2*>(plo);
            float2 p2 = *reinterpret_cast<const float2*>(plo + 8);
            float2 p1 = *reinterpret_cast<const float2*>(phi);
            float2 p3 = *reinterpret_cast<const float2*>(phi + 8);
            Split s0 = split2(p0.x, p0.y);
            Split s1 = split2(p1.x, p1.y);
            Split s2 = split2(p2.x, p2.y);
            Split s3 = split2(p3.x, p3.y);
            Ahi[t][0] = s0.hi; Alo[t][0] = s0.lo;
            Ahi[t][1] = s1.hi; Alo[t][1] = s1.lo;
            Ahi[t][2] = s2.hi; Alo[t][2] = s2.lo;
            Ahi[t][3] = s3.hi; Alo[t][3] = s3.lo;
        }
        const uint2* bp_hi = reinterpret_cast<const uint2*>(
            smu + ((ks * 4 + s4) * 72 + q) * 2);
        const uint2* bp_lo = reinterpret_cast<const uint2*>(
            smu + ((32 + ks * 4 + s4) * 72 + q) * 2);
#pragma unroll
        for (int nt = 0; nt < 8; nt++) {
            uint2 bh = bp_hi[nt * 8];
            uint2 bl = bp_lo[nt * 8];
#pragma unroll
            for (int t = 0; t < 2; t++) {
                mma_bf16(d1[t][nt], Ahi[t], bh.x, bh.y);
                mma_bf16(d1[t][nt], Ahi[t], bl.x, bl.y);
                mma_bf16(d1[t][nt], Alo[t], bh.x, bh.y);
            }
        }
    }

    // ======================= per-tile epilogue ===============================
    float temp = expf(log_temp[0]);
    temp = fminf(fmaxf(temp, 0.5f), 5.0f);
    const float it = 1.0f / temp;
    const float bg0 = par[P_BG], bg1 = par[P_BG + 1];

#pragma unroll
    for (int t = 0; t < 2; t++) {
        // ---- bias + LayerNorm + GELU (in place into d1[t]) -----------------
#pragma unroll
        for (int nt = 0; nt < 8; nt++) {
            float2 bp = *reinterpret_cast<const float2*>(par + P_B1 + nt * 8 + s4 * 2);
            d1[t][nt][0] += bp.x; d1[t][nt][1] += bp.y;
            d1[t][nt][2] += bp.x; d1[t][nt][3] += bp.y;
        }
        float slo = 0.f, shi = 0.f;
#pragma unroll
        for (int nt = 0; nt < 8; nt++) {
            slo += d1[t][nt][0] + d1[t][nt][1];
            shi += d1[t][nt][2] + d1[t][nt][3];
        }
        slo += __shfl_xor_sync(0xffffffffu, slo, 1);
        slo += __shfl_xor_sync(0xffffffffu, slo, 2);
        shi += __shfl_xor_sync(0xffffffffu, shi, 1);
        shi += __shfl_xor_sync(0xffffffffu, shi, 2);
        float mulo = slo * (1.0f / 64.0f);
        float muhi = shi * (1.0f / 64.0f);
        float vlo = 0.f, vhi = 0.f;
#pragma unroll
        for (int nt = 0; nt < 8; nt++) {
            float a0 = d1[t][nt][0] - mulo, a1 = d1[t][nt][1] - mulo;
            float a2 = d1[t][nt][2] - muhi, a3 = d1[t][nt][3] - muhi;
            vlo += a0 * a0 + a1 * a1;
            vhi += a2 * a2 + a3 * a3;
        }
        vlo += __shfl_xor_sync(0xffffffffu, vlo, 1);
        vlo += __shfl_xor_sync(0xffffffffu, vlo, 2);
        vhi += __shfl_xor_sync(0xffffffffu, vhi, 1);
        vhi += __shfl_xor_sync(0xffffffffu, vhi, 2);
        float rstdlo = rsqrtf(vlo * (1.0f / 64.0f) + 1e-5f);
        float rstdhi = rsqrtf(vhi * (1.0f / 64.0f) + 1e-5f);
#pragma unroll
        for (int nt = 0; nt < 8; nt++) {
            float2 gm = *reinterpret_cast<const float2*>(par + P_GM + nt * 8 + s4 * 2);
            float2 bt = *reinterpret_cast<const float2*>(par + P_BT + nt * 8 + s4 * 2);
            d1[t][nt][0] = gelu(gm.x * (d1[t][nt][0] - mulo) * rstdlo + bt.x);
            d1[t][nt][1] = gelu(gm.y * (d1[t][nt][1] - mulo) * rstdlo + bt.y);
            d1[t][nt][2] = gelu(gm.x * (d1[t][nt][2] - muhi) * rstdhi + bt.x);
            d1[t][nt][3] = gelu(gm.y * (d1[t][nt][3] - muhi) * rstdhi + bt.y);
        }

        // ---- layer 2: per-k2 A-frag pack + MMA (only 8 A regs live) --------
        float d2[4][4];
#pragma unroll
        for (int nt = 0; nt < 4; nt++)
#pragma unroll
            for (int j = 0; j < 4; j++) d2[nt][j] = 0.f;

#pragma unroll
        for (int k2 = 0; k2 < 4; k2++) {
            uint32_t A2h[4], A2l[4];
            {
                Split s0 = split2(d1[t][2 * k2][0],     d1[t][2 * k2][1]);
                Split s1 = split2(d1[t][2 * k2][2],     d1[t][2 * k2][3]);
                Split s2 = split2(d1[t][2 * k2 + 1][0], d1[t][2 * k2 + 1][1]);
                Split s3 = split2(d1[t][2 * k2 + 1][2], d1[t][2 * k2 + 1][3]);
                A2h[0] = s0.hi; A2l[0] = s0.lo;
                A2h[1] = s1.hi; A2l[1] = s1.lo;
                A2h[2] = s2.hi; A2l[2] = s2.lo;
                A2h[3] = s3.hi; A2l[3] = s3.lo;
            }
            const uint2* bp_hi = reinterpret_cast<const uint2*>(
                smu + B2F + ((k2 * 4 + s4) * 40 + q) * 2);
            const uint2* bp_lo = reinterpret_cast<const uint2*>(
                smu + B2F + ((16 + k2 * 4 + s4) * 40 + q) * 2);
#pragma unroll
            for (int nt = 0; nt < 4; nt++) {
                uint2 bh = bp_hi[nt * 8];
                uint2 bl = bp_lo[nt * 8];
                mma_bf16(d2[nt], A2h, bh.x, bh.y);
                mma_bf16(d2[nt], A2h, bl.x, bl.y);
                mma_bf16(d2[nt], A2l, bh.x, bh.y);
            }
        }

        // ---- bias + GELU + heads -------------------------------------------
        long growlo = warpRow + t * 16 + q;
        long growhi = growlo + 8;
        int rrlo = regime[growlo > Bm1 ? Bm1 : growlo];
        int rrhi = regime[growhi > Bm1 ? Bm1 : growhi];

        float hh[4][4];
#pragma unroll
        for (int nt = 0; nt < 4; nt++) {
            float2 bp = *reinterpret_cast<const float2*>(par + P_B2 + nt * 8 + s4 * 2);
            hh[nt][0] = gelu(d2[nt][0] + bp.x);
            hh[nt][1] = gelu(d2[nt][1] + bp.y);
            hh[nt][2] = gelu(d2[nt][2] + bp.x);
            hh[nt][3] = gelu(d2[nt][3] + bp.y);
        }

        float galo = 0.f, gblo = 0.f, ralo = 0.f, rblo = 0.f, g2alo = 0.f, g2blo = 0.f;
        float gahi = 0.f, gbhi = 0.f, rahi = 0.f, rbhi = 0.f, g2ahi = 0.f, g2bhi = 0.f;
#pragma unroll
        for (int nt = 0; nt < 4; nt++) {
            int c = nt * 8 + s4 * 2;
            float2 w0 = *reinterpret_cast<const float2*>(par + P_WG + c);
            float2 w1 = *reinterpret_cast<const float2*>(par + P_WG + 32 + c);
            float2 sl = *reinterpret_cast<const float2*>(par + P_SG + rrlo * 36 + c);
            float2 sh = *reinterpret_cast<const float2*>(par + P_SG + rrhi * 36 + c);
            float2 rl0 = *reinterpret_cast<const float2*>(par + P_WR + rrlo * 72 + c);
            float2 rl1 = *reinterpret_cast<const float2*>(par + P_WR + rrlo * 72 + 36 + c);
            float2 rh0 = *reinterpret_cast<const float2*>(par + P_WR + rrhi * 72 + c);
            float2 rh1 = *reinterpret_cast<const float2*>(par + P_WR + rrhi * 72 + 36 + c);

            float h0 = hh[nt][0], h1 = hh[nt][1], h2 = hh[nt][2], h3 = hh[nt][3];
            galo += h0 * w0.x + h1 * w0.y;   gblo += h0 * w1.x + h1 * w1.y;
            gahi += h2 * w0.x + h3 * w0.y;   gbhi += h2 * w1.x + h3 * w1.y;
            ralo += h0 * rl0.x + h1 * rl0.y; rblo += h0 * rl1.x + h1 * rl1.y;
            rahi += h2 * rh0.x + h3 * rh0.y; rbhi += h2 * rh1.x + h3 * rh1.y;
            float e0 = h0 * sl.x, e1 = h1 * sl.y;
            float e2 = h2 * sh.x, e3 = h3 * sh.y;
            g2alo += e0 * w0.x + e1 * w0.y;  g2blo += e0 * w1.x + e1 * w1.y;
            g2ahi += e2 * w0.x + e3 * w0.y;  g2bhi += e2 * w1.x + e3 * w1.y;
        }
#pragma unroll
        for (int d = 1; d <= 2; d <<= 1) {
            galo += __shfl_xor_sync(0xffffffffu, galo, d);
            gblo += __shfl_xor_sync(0xffffffffu, gblo, d);
            ralo += __shfl_xor_sync(0xffffffffu, ralo, d);
            rblo += __shfl_xor_sync(0xffffffffu, rblo, d);
            g2alo += __shfl_xor_sync(0xffffffffu, g2alo, d);
            g2blo += __shfl_xor_sync(0xffffffffu, g2blo, d);
            gahi += __shfl_xor_sync(0xffffffffu, gahi, d);
            gbhi += __shfl_xor_sync(0xffffffffu, gbhi, d);
            rahi += __shfl_xor_sync(0xffffffffu, rahi, d);
            rbhi += __shfl_xor_sync(0xffffffffu, rbhi, d);
            g2ahi += __shfl_xor_sync(0xffffffffu, g2ahi, d);
            g2bhi += __shfl_xor_sync(0xffffffffu, g2bhi, d);
        }

        if (s4 == 0) {
            if (growlo < B) {
                float2 o;
                o.x = (0.5f * (galo + bg0) + 0.3f * (ralo + par[P_BR + rrlo * 2]) +
                       0.2f * (g2alo + bg0)) * it;
                o.y = (0.5f * (gblo + bg1) + 0.3f * (rblo + par[P_BR + rrlo * 2 + 1]) +
                       0.2f * (g2blo + bg1)) * it;
                reinterpret_cast<float2*>(out)[growlo] = o;
            }
            if (growhi < B) {
                float2 o;
                o.x = (0.5f * (gahi + bg0) + 0.3f * (rahi + par[P_BR + rrhi * 2]) +
                       0.2f * (g2ahi + bg0)) * it;
                o.y = (0.5f * (gbhi + bg1) + 0.3f * (rbhi + par[P_BR + rrhi * 2 + 1]) +
                       0.2f * (g2bhi + bg1)) * it;
                reinterpret_cast<float2*>(out)[growhi] = o;
            }
        }
    }
}

extern "C" void kernel_launch(void* const* d_in, const int* in_sizes, int n_in,
                              void* d_out, int out_size)
{
    const float* x        = (const float*)d_in[0];
    const int*   regime   = (const int*)  d_in[1];
    const float* W1       = (const float*)d_in[2];
    const float* b1       = (const float*)d_in[3];
    const float* gamma    = (const float*)d_in[4];
    const float* beta     = (const float*)d_in[5];
    const float* W2       = (const float*)d_in[6];
    const float* b2       = (const float*)d_in[7];
    const float* Wg       = (const float*)d_in[8];
    const float* bg       = (const float*)d_in[9];
    const float* Wr       = (const float*)d_in[10];
    const float* br       = (const float*)d_in[11];
    const float* emb      = (const float*)d_in[12];
    const float* log_temp = (const float*)d_in[13];
    float* out = (float*)d_out;

    const int B = in_sizes[1];
    const int grid = (B + ROWS - 1) / ROWS;

    cudaFuncSetAttribute(nml_mma_kernel,
                         cudaFuncAttributeMaxDynamicSharedMemorySize, SMEM_BYTES);
    nml_mma_kernel<<<grid, TPB, SMEM_BYTES>>>(x, regime, W1, b1, gamma, beta,
                                              W2, b2, Wg, bg, Wr, br, emb,
                                              log_temp, out, B);
}

// round 7
// speedup vs baseline: 3.6286x; 1.1117x over previous
#include <cuda_runtime.h>
#include <cuda_bf16.h>
#include <cstdint>

// ---------------------------------------------------------------------------
// Round 7: R6 with the B-fragment uint2 indexing bug fixed (nt*4 -> nt*8).
//  - B-fragment smem strides 68/36 pairs -> conflict-free LDS.64
//    (pair-bank = s4*4 + q, all 16 distinct per half-warp)
//  - x loaded as LDG.128 under a consistent K-permutation (A slots and the
//    W1 B-fragment packing both use mem col c = ks*16 + 4*s4 + 2*j + o).
// ---------------------------------------------------------------------------

constexpr int TPB  = 256;
constexpr int ROWS = 256;

// smem word offsets
constexpr int B1F = 0;        // W1 frags: 64 groups * 68 pairs * 2 words = 8704
constexpr int B2F = 8704;     // W2 frags: 32 groups * 36 pairs * 2 words = 2304
constexpr int PAR = 11008;    // float params (736 words)
constexpr int P_B1 = 0, P_GM = 64, P_BT = 128, P_B2 = 192, P_WG = 224,
              P_BG = 288, P_BR = 290, P_SG = 304, P_WR = 448; // end 736
constexpr int SMEM_BYTES = (11008 + 736) * 4;   // 46976

static __device__ __forceinline__ void mma_bf16(float d[4], const uint32_t a[4],
                                                uint32_t b0, uint32_t b1) {
    asm volatile(
        "mma.sync.aligned.m16n8k16.row.col.f32.bf16.bf16.f32 "
        "{%0,%1,%2,%3}, {%4,%5,%6,%7}, {%8,%9}, {%0,%1,%2,%3};"
        : "+f"(d[0]), "+f"(d[1]), "+f"(d[2]), "+f"(d[3])
        : "r"(a[0]), "r"(a[1]), "r"(a[2]), "r"(a[3]), "r"(b0), "r"(b1));
}

struct Split { uint32_t hi, lo; };
static __device__ __forceinline__ Split split2(float a, float b) {
    Split s;
    asm("cvt.rn.bf16x2.f32 %0, %1, %2;" : "=r"(s.hi) : "f"(b), "f"(a));
    float ha = __uint_as_float(s.hi << 16);
    float hb = __uint_as_float(s.hi & 0xFFFF0000u);
    asm("cvt.rn.bf16x2.f32 %0, %1, %2;" : "=r"(s.lo) : "f"(b - hb), "f"(a - ha));
    return s;
}

static __device__ __forceinline__ float rcp_fast(float x) {
    float r; asm("rcp.approx.f32 %0, %1;" : "=f"(r) : "f"(x)); return r;
}
static __device__ __forceinline__ float ex2_fast(float x) {
    float r; asm("ex2.approx.f32 %0, %1;" : "=f"(r) : "f"(x)); return r;
}
// branchless exact-erf GELU (A&S 7.1.26, |erf err| <= 1.5e-7)
static __device__ __forceinline__ float gelu(float v) {
    float x = fabsf(v) * 0.70710678118654752440f;
    float t = rcp_fast(fmaf(0.3275911f, x, 1.0f));
    float p = fmaf(1.061405429f, t, -1.453152027f);
    p = fmaf(p, t, 1.421413741f);
    p = fmaf(p, t, -0.284496736f);
    p = fmaf(p, t, 0.254829592f);
    p = p * t;
    float e = ex2_fast(x * x * -1.4426950408889634f);
    float erf_ = 1.0f - p * e;
    return fmaf(0.5f * fabsf(v), erf_, 0.5f * v);
}

__global__ __launch_bounds__(TPB, 2)
void nml_mma_kernel(
    const float* __restrict__ x, const int* __restrict__ regime,
    const float* __restrict__ W1, const float* __restrict__ b1,
    const float* __restrict__ gamma, const float* __restrict__ beta,
    const float* __restrict__ W2, const float* __restrict__ b2,
    const float* __restrict__ Wg, const float* __restrict__ bg,
    const float* __restrict__ Wr, const float* __restrict__ br,
    const float* __restrict__ emb, const float* __restrict__ log_temp,
    float* __restrict__ out, int B)
{
    extern __shared__ float smem[];
    uint32_t* smu = reinterpret_cast<uint32_t*>(smem);
    float* par = smem + PAR;

    const int tid = threadIdx.x;

    // ---- W1 -> split-bf16 B frags, K-permuted decode, stride 68 pairs ------
    // mem col pair cp = ks*8 + sq*2 + j  (mem cols 2cp, 2cp+1)
#pragma unroll
    for (int it = 0; it < 4096 / TPB; it++) {
        int i = it * TPB + tid;
        int n = i >> 6, cp = i & 63;
        int ks = cp >> 3, r = cp & 7, sq = r >> 1, j = r & 1;
        float2 wv = *reinterpret_cast<const float2*>(W1 + n * 128 + cp * 2);
        Split s = split2(wv.x, wv.y);
        smu[B1F + ((ks * 4 + sq) * 68 + n) * 2 + j]        = s.hi;
        smu[B1F + ((32 + ks * 4 + sq) * 68 + n) * 2 + j]   = s.lo;
    }
    // ---- W2 (natural decode: layer-2 A comes straight from D1), stride 36 --
#pragma unroll
    for (int it = 0; it < 1024 / TPB; it++) {
        int i = it * TPB + tid;
        int n = i >> 5, kpg = i & 31;
        int k2 = kpg >> 3, r = kpg & 7, sq = r & 3, j = r >> 2;
        float2 wv = *reinterpret_cast<const float2*>(W2 + n * 64 + kpg * 2);
        Split s = split2(wv.x, wv.y);
        smu[B2F + ((k2 * 4 + sq) * 36 + n) * 2 + j]        = s.hi;
        smu[B2F + ((16 + k2 * 4 + sq) * 36 + n) * 2 + j]   = s.lo;
    }
    // ---- params -------------------------------------------------------------
    if (tid < 64) {
        par[P_B1 + tid] = b1[tid];
        par[P_GM + tid] = gamma[tid];
        par[P_BT + tid] = beta[tid];
        par[P_WG + tid] = Wg[tid];
    }
    if (tid < 32) par[P_B2 + tid] = b2[tid];
    if (tid < 2)  par[P_BG + tid] = bg[tid];
    if (tid < 8)  par[P_BR + tid] = br[tid];
    if (tid < 128) {
        int rr = tid >> 5, c = tid & 31;
        par[P_SG + rr * 36 + c] = 1.0f / (1.0f + expf(-emb[tid]));
    }
    {
        int rr = tid >> 6, hf = (tid >> 5) & 1, c = tid & 31;
        par[P_WR + rr * 72 + hf * 36 + c] = Wr[tid];
    }
    __syncthreads();

    const int wid  = tid >> 5;
    const int lane = tid & 31;
    const int q    = lane >> 2;     // 0..7
    const int s4   = lane & 3;      // 0..3
    const long warpRow = (long)blockIdx.x * ROWS + wid * 32;
    const long Bm1 = B - 1;

    // ======================= layer 1: D1 = X @ W1^T =========================
    float d1[2][8][4];
#pragma unroll
    for (int t = 0; t < 2; t++)
#pragma unroll
        for (int nt = 0; nt < 8; nt++)
#pragma unroll
            for (int j = 0; j < 4; j++) d1[t][nt][j] = 0.f;

#pragma unroll 2
    for (int ks = 0; ks < 8; ks++) {
        uint32_t Ahi[2][4], Alo[2][4];
#pragma unroll
        for (int t = 0; t < 2; t++) {
            long rlo = warpRow + t * 16 + q;
            long rhi = rlo + 8;
            if (rlo > Bm1) rlo = Bm1;
            if (rhi > Bm1) rhi = Bm1;
            // one LDG.128 per row: mem cols ks*16 + 4*s4 .. +3 hold this
            // lane's fragment k-slots under the K-permutation
            float4 vlo = *reinterpret_cast<const float4*>(
                x + rlo * 128 + ks * 16 + s4 * 4);
            float4 vhi = *reinterpret_cast<const float4*>(
                x + rhi * 128 + ks * 16 + s4 * 4);
            Split s0 = split2(vlo.x, vlo.y);
            Split s1 = split2(vhi.x, vhi.y);
            Split s2 = split2(vlo.z, vlo.w);
            Split s3 = split2(vhi.z, vhi.w);
            Ahi[t][0] = s0.hi; Alo[t][0] = s0.lo;
            Ahi[t][1] = s1.hi; Alo[t][1] = s1.lo;
            Ahi[t][2] = s2.hi; Alo[t][2] = s2.lo;
            Ahi[t][3] = s3.hi; Alo[t][3] = s3.lo;
        }
        const uint2* bp_hi = reinterpret_cast<const uint2*>(
            smu + ((ks * 4 + s4) * 68 + q) * 2);
        const uint2* bp_lo = reinterpret_cast<const uint2*>(
            smu + ((32 + ks * 4 + s4) * 68 + q) * 2);
#pragma unroll
        for (int nt = 0; nt < 8; nt++) {
            uint2 bh = bp_hi[nt * 8];   // n += 8 -> +8 uint2 (one pair per n)
            uint2 bl = bp_lo[nt * 8];
#pragma unroll
            for (int t = 0; t < 2; t++) {
                mma_bf16(d1[t][nt], Ahi[t], bh.x, bh.y);
                mma_bf16(d1[t][nt], Ahi[t], bl.x, bl.y);
                mma_bf16(d1[t][nt], Alo[t], bh.x, bh.y);
            }
        }
    }

    // ======================= per-tile epilogue ===============================
    float temp = expf(log_temp[0]);
    temp = fminf(fmaxf(temp, 0.5f), 5.0f);
    const float it = 1.0f / temp;
    const float bg0 = par[P_BG], bg1 = par[P_BG + 1];

#pragma unroll
    for (int t = 0; t < 2; t++) {
        // ---- bias + LayerNorm + GELU (in place) -----------------------------
#pragma unroll
        for (int nt = 0; nt < 8; nt++) {
            float2 bp = *reinterpret_cast<const float2*>(par + P_B1 + nt * 8 + s4 * 2);
            d1[t][nt][0] += bp.x; d1[t][nt][1] += bp.y;
            d1[t][nt][2] += bp.x; d1[t][nt][3] += bp.y;
        }
        float slo = 0.f, shi = 0.f;
#pragma unroll
        for (int nt = 0; nt < 8; nt++) {
            slo += d1[t][nt][0] + d1[t][nt][1];
            shi += d1[t][nt][2] + d1[t][nt][3];
        }
        slo += __shfl_xor_sync(0xffffffffu, slo, 1);
        slo += __shfl_xor_sync(0xffffffffu, slo, 2);
        shi += __shfl_xor_sync(0xffffffffu, shi, 1);
        shi += __shfl_xor_sync(0xffffffffu, shi, 2);
        float mulo = slo * (1.0f / 64.0f);
        float muhi = shi * (1.0f / 64.0f);
        float vlo = 0.f, vhi = 0.f;
#pragma unroll
        for (int nt = 0; nt < 8; nt++) {
            float a0 = d1[t][nt][0] - mulo, a1 = d1[t][nt][1] - mulo;
            float a2 = d1[t][nt][2] - muhi, a3 = d1[t][nt][3] - muhi;
            vlo += a0 * a0 + a1 * a1;
            vhi += a2 * a2 + a3 * a3;
        }
        vlo += __shfl_xor_sync(0xffffffffu, vlo, 1);
        vlo += __shfl_xor_sync(0xffffffffu, vlo, 2);
        vhi += __shfl_xor_sync(0xffffffffu, vhi, 1);
        vhi += __shfl_xor_sync(0xffffffffu, vhi, 2);
        float rstdlo = rsqrtf(vlo * (1.0f / 64.0f) + 1e-5f);
        float rstdhi = rsqrtf(vhi * (1.0f / 64.0f) + 1e-5f);
#pragma unroll
        for (int nt = 0; nt < 8; nt++) {
            float2 gm = *reinterpret_cast<const float2*>(par + P_GM + nt * 8 + s4 * 2);
            float2 bt = *reinterpret_cast<const float2*>(par + P_BT + nt * 8 + s4 * 2);
            d1[t][nt][0] = gelu(gm.x * (d1[t][nt][0] - mulo) * rstdlo + bt.x);
            d1[t][nt][1] = gelu(gm.y * (d1[t][nt][1] - mulo) * rstdlo + bt.y);
            d1[t][nt][2] = gelu(gm.x * (d1[t][nt][2] - muhi) * rstdhi + bt.x);
            d1[t][nt][3] = gelu(gm.y * (d1[t][nt][3] - muhi) * rstdhi + bt.y);
        }

        // ---- layer 2: per-k2 A-frag pack + MMA -------------------------------
        float d2[4][4];
#pragma unroll
        for (int nt = 0; nt < 4; nt++)
#pragma unroll
            for (int j = 0; j < 4; j++) d2[nt][j] = 0.f;

#pragma unroll
        for (int k2 = 0; k2 < 4; k2++) {
            uint32_t A2h[4], A2l[4];
            {
                Split s0 = split2(d1[t][2 * k2][0],     d1[t][2 * k2][1]);
                Split s1 = split2(d1[t][2 * k2][2],     d1[t][2 * k2][3]);
                Split s2 = split2(d1[t][2 * k2 + 1][0], d1[t][2 * k2 + 1][1]);
                Split s3 = split2(d1[t][2 * k2 + 1][2], d1[t][2 * k2 + 1][3]);
                A2h[0] = s0.hi; A2l[0] = s0.lo;
                A2h[1] = s1.hi; A2l[1] = s1.lo;
                A2h[2] = s2.hi; A2l[2] = s2.lo;
                A2h[3] = s3.hi; A2l[3] = s3.lo;
            }
            const uint2* bp_hi = reinterpret_cast<const uint2*>(
                smu + B2F + ((k2 * 4 + s4) * 36 + q) * 2);
            const uint2* bp_lo = reinterpret_cast<const uint2*>(
                smu + B2F + ((16 + k2 * 4 + s4) * 36 + q) * 2);
#pragma unroll
            for (int nt = 0; nt < 4; nt++) {
                uint2 bh = bp_hi[nt * 8];
                uint2 bl = bp_lo[nt * 8];
                mma_bf16(d2[nt], A2h, bh.x, bh.y);
                mma_bf16(d2[nt], A2h, bl.x, bl.y);
                mma_bf16(d2[nt], A2l, bh.x, bh.y);
            }
        }

        // ---- bias + GELU + heads ---------------------------------------------
        long growlo = warpRow + t * 16 + q;
        long growhi = growlo + 8;
        int rrlo = regime[growlo > Bm1 ? Bm1 : growlo];
        int rrhi = regime[growhi > Bm1 ? Bm1 : growhi];

        float hh[4][4];
#pragma unroll
        for (int nt = 0; nt < 4; nt++) {
            float2 bp = *reinterpret_cast<const float2*>(par + P_B2 + nt * 8 + s4 * 2);
            hh[nt][0] = gelu(d2[nt][0] + bp.x);
            hh[nt][1] = gelu(d2[nt][1] + bp.y);
            hh[nt][2] = gelu(d2[nt][2] + bp.x);
            hh[nt][3] = gelu(d2[nt][3] + bp.y);
        }

        float galo = 0.f, gblo = 0.f, ralo = 0.f, rblo = 0.f, g2alo = 0.f, g2blo = 0.f;
        float gahi = 0.f, gbhi = 0.f, rahi = 0.f, rbhi = 0.f, g2ahi = 0.f, g2bhi = 0.f;
#pragma unroll
        for (int nt = 0; nt < 4; nt++) {
            int c = nt * 8 + s4 * 2;
            float2 w0 = *reinterpret_cast<const float2*>(par + P_WG + c);
            float2 w1 = *reinterpret_cast<const float2*>(par + P_WG + 32 + c);
            float2 sl = *reinterpret_cast<const float2*>(par + P_SG + rrlo * 36 + c);
            float2 sh = *reinterpret_cast<const float2*>(par + P_SG + rrhi * 36 + c);
            float2 rl0 = *reinterpret_cast<const float2*>(par + P_WR + rrlo * 72 + c);
            float2 rl1 = *reinterpret_cast<const float2*>(par + P_WR + rrlo * 72 + 36 + c);
            float2 rh0 = *reinterpret_cast<const float2*>(par + P_WR + rrhi * 72 + c);
            float2 rh1 = *reinterpret_cast<const float2*>(par + P_WR + rrhi * 72 + 36 + c);

            float h0 = hh[nt][0], h1 = hh[nt][1], h2 = hh[nt][2], h3 = hh[nt][3];
            galo += h0 * w0.x + h1 * w0.y;   gblo += h0 * w1.x + h1 * w1.y;
            gahi += h2 * w0.x + h3 * w0.y;   gbhi += h2 * w1.x + h3 * w1.y;
            ralo += h0 * rl0.x + h1 * rl0.y; rblo += h0 * rl1.x + h1 * rl1.y;
            rahi += h2 * rh0.x + h3 * rh0.y; rbhi += h2 * rh1.x + h3 * rh1.y;
            float e0 = h0 * sl.x, e1 = h1 * sl.y;
            float e2 = h2 * sh.x, e3 = h3 * sh.y;
            g2alo += e0 * w0.x + e1 * w0.y;  g2blo += e0 * w1.x + e1 * w1.y;
            g2ahi += e2 * w0.x + e3 * w0.y;  g2bhi += e2 * w1.x + e3 * w1.y;
        }
#pragma unroll
        for (int d = 1; d <= 2; d <<= 1) {
            galo += __shfl_xor_sync(0xffffffffu, galo, d);
            gblo += __shfl_xor_sync(0xffffffffu, gblo, d);
            ralo += __shfl_xor_sync(0xffffffffu, ralo, d);
            rblo += __shfl_xor_sync(0xffffffffu, rblo, d);
            g2alo += __shfl_xor_sync(0xffffffffu, g2alo, d);
            g2blo += __shfl_xor_sync(0xffffffffu, g2blo, d);
            gahi += __shfl_xor_sync(0xffffffffu, gahi, d);
            gbhi += __shfl_xor_sync(0xffffffffu, gbhi, d);
            rahi += __shfl_xor_sync(0xffffffffu, rahi, d);
            rbhi += __shfl_xor_sync(0xffffffffu, rbhi, d);
            g2ahi += __shfl_xor_sync(0xffffffffu, g2ahi, d);
            g2bhi += __shfl_xor_sync(0xffffffffu, g2bhi, d);
        }

        if (s4 == 0) {
            if (growlo < B) {
                float2 o;
                o.x = (0.5f * (galo + bg0) + 0.3f * (ralo + par[P_BR + rrlo * 2]) +
                       0.2f * (g2alo + bg0)) * it;
                o.y = (0.5f * (gblo + bg1) + 0.3f * (rblo + par[P_BR + rrlo * 2 + 1]) +
                       0.2f * (g2blo + bg1)) * it;
                reinterpret_cast<float2*>(out)[growlo] = o;
            }
            if (growhi < B) {
                float2 o;
                o.x = (0.5f * (gahi + bg0) + 0.3f * (rahi + par[P_BR + rrhi * 2]) +
                       0.2f * (g2ahi + bg0)) * it;
                o.y = (0.5f * (gbhi + bg1) + 0.3f * (rbhi + par[P_BR + rrhi * 2 + 1]) +
                       0.2f * (g2bhi + bg1)) * it;
                reinterpret_cast<float2*>(out)[growhi] = o;
            }
        }
    }
}

extern "C" void kernel_launch(void* const* d_in, const int* in_sizes, int n_in,
                              void* d_out, int out_size)
{
    const float* x        = (const float*)d_in[0];
    const int*   regime   = (const int*)  d_in[1];
    const float* W1       = (const float*)d_in[2];
    const float* b1       = (const float*)d_in[3];
    const float* gamma    = (const float*)d_in[4];
    const float* beta     = (const float*)d_in[5];
    const float* W2       = (const float*)d_in[6];
    const float* b2       = (const float*)d_in[7];
    const float* Wg       = (const float*)d_in[8];
    const float* bg       = (const float*)d_in[9];
    const float* Wr       = (const float*)d_in[10];
    const float* br       = (const float*)d_in[11];
    const float* emb      = (const float*)d_in[12];
    const float* log_temp = (const float*)d_in[13];
    float* out = (float*)d_out;

    const int B = in_sizes[1];
    const int grid = (B + ROWS - 1) / ROWS;

    cudaFuncSetAttribute(nml_mma_kernel,
                         cudaFuncAttributeMaxDynamicSharedMemorySize, SMEM_BYTES);
    nml_mma_kernel<<<grid, TPB, SMEM_BYTES>>>(x, regime, W1, b1, gamma, beta,
                                              W2, b2, Wg, bg, Wr, br, emb,
                                              log_temp, out, B);
}

// round 8
// speedup vs baseline: 4.0221x; 1.1084x over previous
#include <cuda_runtime.h>
#include <cuda_bf16.h>
#include <cstdint>

// ---------------------------------------------------------------------------
// Round 8: R7 + packed-f32x2 epilogue (LN/GELU/bias), merged g+g2 head,
// MMA term round-robin for dep distance, int32 indexing.
// Layouts identical to R7 (stride-68/36 B-frags, K-permuted x LDG.128).
// ---------------------------------------------------------------------------

typedef unsigned long long u64;

constexpr int TPB  = 256;
constexpr int ROWS = 256;

// smem word offsets
constexpr int B1F = 0;        // W1 frags: 64 groups * 68 pairs * 2 words
constexpr int B2F = 8704;     // W2 frags: 32 groups * 36 pairs * 2 words
constexpr int PAR = 11008;
constexpr int P_B1 = 0, P_GM = 64, P_BT = 128, P_B2 = 192, P_WG = 224,
              P_BG = 288, P_BR = 290, P_SG = 304, P_WR = 448; // end 704
constexpr int SMEM_BYTES = (11008 + 704) * 4;

static __device__ __forceinline__ void mma_bf16(float d[4], const uint32_t a[4],
                                                uint32_t b0, uint32_t b1) {
    asm volatile(
        "mma.sync.aligned.m16n8k16.row.col.f32.bf16.bf16.f32 "
        "{%0,%1,%2,%3}, {%4,%5,%6,%7}, {%8,%9}, {%0,%1,%2,%3};"
        : "+f"(d[0]), "+f"(d[1]), "+f"(d[2]), "+f"(d[3])
        : "r"(a[0]), "r"(a[1]), "r"(a[2]), "r"(a[3]), "r"(b0), "r"(b1));
}

struct Split { uint32_t hi, lo; };
static __device__ __forceinline__ Split split2(float a, float b) {
    Split s;
    asm("cvt.rn.bf16x2.f32 %0, %1, %2;" : "=r"(s.hi) : "f"(b), "f"(a));
    float ha = __uint_as_float(s.hi << 16);
    float hb = __uint_as_float(s.hi & 0xFFFF0000u);
    asm("cvt.rn.bf16x2.f32 %0, %1, %2;" : "=r"(s.lo) : "f"(b - hb), "f"(a - ha));
    return s;
}

static __device__ __forceinline__ u64 pk2(float x, float y) {
    u64 r; asm("mov.b64 %0, {%1, %2};" : "=l"(r) : "f"(x), "f"(y)); return r;
}
static __device__ __forceinline__ float2 unpk(u64 v) {
    float2 f; asm("mov.b64 {%0, %1}, %2;" : "=f"(f.x), "=f"(f.y) : "l"(v)); return f;
}
#define FMA2(d, a, b, c) asm("fma.rn.f32x2 %0, %1, %2, %3;" : "=l"(d) : "l"(a), "l"(b), "l"(c))
#define MUL2(d, a, b)    asm("mul.rn.f32x2 %0, %1, %2;"     : "=l"(d) : "l"(a), "l"(b))
#define ADD2(d, a, b)    asm("add.rn.f32x2 %0, %1, %2;"     : "=l"(d) : "l"(a), "l"(b))

static __device__ __forceinline__ float rcp_fast(float x) {
    float r; asm("rcp.approx.f32 %0, %1;" : "=f"(r) : "f"(x)); return r;
}
static __device__ __forceinline__ float ex2_fast(float x) {
    float r; asm("ex2.approx.f32 %0, %1;" : "=f"(r) : "f"(x)); return r;
}
static __device__ __forceinline__ Split split2p(u64 v2) {
    float2 f = unpk(v2);
    return split2(f.x, f.y);
}

// packed branchless exact-erf GELU (A&S 7.1.26), 2 values per call
static __device__ __forceinline__ u64 gelu2(u64 v2) {
    u64 av;
    asm("and.b64 %0, %1, %2;" : "=l"(av) : "l"(v2), "l"(0x7FFFFFFF7FFFFFFFull));
    const float IS2 = 0.70710678118654752440f;
    u64 x2;  MUL2(x2, av, pk2(IS2, IS2));                       // |v|/sqrt2
    u64 u;   FMA2(u, x2, pk2(0.3275911f, 0.3275911f), pk2(1.f, 1.f));
    float2 uf = unpk(u);
    u64 t2 = pk2(rcp_fast(uf.x), rcp_fast(uf.y));
    u64 p;
    FMA2(p, t2, pk2(1.061405429f, 1.061405429f), pk2(-1.453152027f, -1.453152027f));
    FMA2(p, p, t2, pk2(1.421413741f, 1.421413741f));
    FMA2(p, p, t2, pk2(-0.284496736f, -0.284496736f));
    FMA2(p, p, t2, pk2(0.254829592f, 0.254829592f));
    MUL2(p, p, t2);
    u64 xx;  MUL2(xx, x2, x2);
    u64 ea;  MUL2(ea, xx, pk2(-1.4426950408889634f, -1.4426950408889634f));
    float2 ef = unpk(ea);
    u64 pe;  MUL2(pe, p, pk2(ex2_fast(ef.x), ex2_fast(ef.y)));
    u64 erf2; FMA2(erf2, pe, pk2(-1.f, -1.f), pk2(1.f, 1.f));   // 1 - p*e
    u64 habs; MUL2(habs, x2, pk2(IS2, IS2));                    // 0.5*|v|
    u64 hv;   MUL2(hv, v2, pk2(0.5f, 0.5f));
    u64 res;  FMA2(res, habs, erf2, hv);
    return res;
}

__global__ __launch_bounds__(TPB, 2)
void nml_mma_kernel(
    const float* __restrict__ x, const int* __restrict__ regime,
    const float* __restrict__ W1, const float* __restrict__ b1,
    const float* __restrict__ gamma, const float* __restrict__ beta,
    const float* __restrict__ W2, const float* __restrict__ b2,
    const float* __restrict__ Wg, const float* __restrict__ bg,
    const float* __restrict__ Wr, const float* __restrict__ br,
    const float* __restrict__ emb, const float* __restrict__ log_temp,
    float* __restrict__ out, int B)
{
    extern __shared__ float smem[];
    uint32_t* smu = reinterpret_cast<uint32_t*>(smem);
    float* par = smem + PAR;

    const int tid = threadIdx.x;

    // ---- W1 -> split-bf16 B frags (K-permuted decode, stride 68 pairs) -----
#pragma unroll
    for (int it = 0; it < 4096 / TPB; it++) {
        int i = it * TPB + tid;
        int n = i >> 6, cp = i & 63;
        int ks = cp >> 3, r = cp & 7, sq = r >> 1, j = r & 1;
        float2 wv = *reinterpret_cast<const float2*>(W1 + n * 128 + cp * 2);
        Split s = split2(wv.x, wv.y);
        smu[B1F + ((ks * 4 + sq) * 68 + n) * 2 + j]      = s.hi;
        smu[B1F + ((32 + ks * 4 + sq) * 68 + n) * 2 + j] = s.lo;
    }
    // ---- W2 (natural decode, stride 36 pairs) -------------------------------
#pragma unroll
    for (int it = 0; it < 1024 / TPB; it++) {
        int i = it * TPB + tid;
        int n = i >> 5, kpg = i & 31;
        int k2 = kpg >> 3, r = kpg & 7, sq = r & 3, j = r >> 2;
        float2 wv = *reinterpret_cast<const float2*>(W2 + n * 64 + kpg * 2);
        Split s = split2(wv.x, wv.y);
        smu[B2F + ((k2 * 4 + sq) * 36 + n) * 2 + j]      = s.hi;
        smu[B2F + ((16 + k2 * 4 + sq) * 36 + n) * 2 + j] = s.lo;
    }
    // ---- params --------------------------------------------------------------
    if (tid < 64) {
        par[P_B1 + tid] = b1[tid];
        par[P_GM + tid] = gamma[tid];
        par[P_BT + tid] = beta[tid];
    }
    if (tid < 32) {
        par[P_B2 + tid] = b2[tid];
        // Wg interleaved pairs: (Wg[0][i], Wg[1][i])
        par[P_WG + 2 * tid]     = Wg[tid];
        par[P_WG + 2 * tid + 1] = Wg[32 + tid];
    }
    if (tid < 2)  par[P_BG + tid] = 0.7f * bg[tid];
    if (tid < 8)  par[P_BR + tid] = 0.3f * br[tid];
    if (tid < 128) {
        int rr = tid >> 5, c = tid & 31;
        par[P_SG + rr * 36 + c] = 0.5f + 0.2f / (1.0f + expf(-emb[tid]));
    }
    {
        // Wr interleaved pairs per regime: (Wr[rr][0][ch], Wr[rr][1][ch])
        int rr = tid >> 6, rest = tid & 63, ch = rest >> 1, sel = rest & 1;
        par[P_WR + rr * 64 + ch * 2 + sel] = Wr[rr * 64 + sel * 32 + ch];
    }
    __syncthreads();

    const int wid  = tid >> 5;
    const int lane = tid & 31;
    const int q    = lane >> 2;
    const int s4   = lane & 3;
    const int warpRow = blockIdx.x * ROWS + wid * 32;
    const int Bm1 = B - 1;

    // ======================= layer 1: D1 = X @ W1^T ==========================
    float d1[2][8][4];
#pragma unroll
    for (int t = 0; t < 2; t++)
#pragma unroll
        for (int nt = 0; nt < 8; nt++)
#pragma unroll
            for (int j = 0; j < 4; j++) d1[t][nt][j] = 0.f;

#pragma unroll 2
    for (int ks = 0; ks < 8; ks++) {
        uint32_t Ahi[2][4], Alo[2][4];
#pragma unroll
        for (int t = 0; t < 2; t++) {
            int rlo = warpRow + t * 16 + q;
            int rhi = rlo + 8;
            if (rlo > Bm1) rlo = Bm1;
            if (rhi > Bm1) rhi = Bm1;
            float4 vlo = *reinterpret_cast<const float4*>(
                x + rlo * 128 + ks * 16 + s4 * 4);
            float4 vhi = *reinterpret_cast<const float4*>(
                x + rhi * 128 + ks * 16 + s4 * 4);
            Split s0 = split2(vlo.x, vlo.y);
            Split s1 = split2(vhi.x, vhi.y);
            Split s2 = split2(vlo.z, vlo.w);
            Split s3 = split2(vhi.z, vhi.w);
            Ahi[t][0] = s0.hi; Alo[t][0] = s0.lo;
            Ahi[t][1] = s1.hi; Alo[t][1] = s1.lo;
            Ahi[t][2] = s2.hi; Alo[t][2] = s2.lo;
            Ahi[t][3] = s3.hi; Alo[t][3] = s3.lo;
        }
        const uint2* bp_hi = reinterpret_cast<const uint2*>(
            smu + ((ks * 4 + s4) * 68 + q) * 2);
        const uint2* bp_lo = reinterpret_cast<const uint2*>(
            smu + ((32 + ks * 4 + s4) * 68 + q) * 2);
#pragma unroll
        for (int np = 0; np < 4; np++) {
            int n0 = 2 * np, n1 = 2 * np + 1;
            uint2 bh0 = bp_hi[n0 * 8], bh1 = bp_hi[n1 * 8];
            uint2 bl0 = bp_lo[n0 * 8], bl1 = bp_lo[n1 * 8];
            // round-robin over 4 accumulators: dep distance 4
            mma_bf16(d1[0][n0], Ahi[0], bh0.x, bh0.y);
            mma_bf16(d1[1][n0], Ahi[1], bh0.x, bh0.y);
            mma_bf16(d1[0][n1], Ahi[0], bh1.x, bh1.y);
            mma_bf16(d1[1][n1], Ahi[1], bh1.x, bh1.y);
            mma_bf16(d1[0][n0], Ahi[0], bl0.x, bl0.y);
            mma_bf16(d1[1][n0], Ahi[1], bl0.x, bl0.y);
            mma_bf16(d1[0][n1], Ahi[0], bl1.x, bl1.y);
            mma_bf16(d1[1][n1], Ahi[1], bl1.x, bl1.y);
            mma_bf16(d1[0][n0], Alo[0], bh0.x, bh0.y);
            mma_bf16(d1[1][n0], Alo[1], bh0.x, bh0.y);
            mma_bf16(d1[0][n1], Alo[0], bh1.x, bh1.y);
            mma_bf16(d1[1][n1], Alo[1], bh1.x, bh1.y);
        }
    }

    // ======================= per-tile epilogue ================================
    float temp = expf(log_temp[0]);
    temp = fminf(fmaxf(temp, 0.5f), 5.0f);
    const float it = 1.0f / temp;

    const u64* b1v = reinterpret_cast<const u64*>(par + P_B1);
    const u64* gmv = reinterpret_cast<const u64*>(par + P_GM);
    const u64* btv = reinterpret_cast<const u64*>(par + P_BT);
    const u64* b2v = reinterpret_cast<const u64*>(par + P_B2);
    const u64* wgv = reinterpret_cast<const u64*>(par + P_WG);

#pragma unroll
    for (int t = 0; t < 2; t++) {
        // ---- bias + pack (lo rows = D regs 0,1; hi rows = 2,3) --------------
        u64 plo[8], phi[8];
#pragma unroll
        for (int nt = 0; nt < 8; nt++) {
            u64 bp = b1v[nt * 4 + s4];
            u64 a = pk2(d1[t][nt][0], d1[t][nt][1]);
            u64 b = pk2(d1[t][nt][2], d1[t][nt][3]);
            ADD2(plo[nt], a, bp);
            ADD2(phi[nt], b, bp);
        }
        // ---- mean -------------------------------------------------------------
        u64 s2l = plo[0], s2h = phi[0];
#pragma unroll
        for (int nt = 1; nt < 8; nt++) { ADD2(s2l, s2l, plo[nt]); ADD2(s2h, s2h, phi[nt]); }
        float2 fl = unpk(s2l), fh = unpk(s2h);
        float slo = fl.x + fl.y, shi = fh.x + fh.y;
        slo += __shfl_xor_sync(0xffffffffu, slo, 1);
        slo += __shfl_xor_sync(0xffffffffu, slo, 2);
        shi += __shfl_xor_sync(0xffffffffu, shi, 1);
        shi += __shfl_xor_sync(0xffffffffu, shi, 2);
        float mulo = slo * (1.0f / 64.0f);
        float muhi = shi * (1.0f / 64.0f);
        // ---- center + variance -------------------------------------------------
        u64 nml = pk2(-mulo, -mulo), nmh = pk2(-muhi, -muhi);
        u64 vl2 = 0ull, vh2 = 0ull;
#pragma unroll
        for (int nt = 0; nt < 8; nt++) {
            ADD2(plo[nt], plo[nt], nml);
            FMA2(vl2, plo[nt], plo[nt], vl2);
            ADD2(phi[nt], phi[nt], nmh);
            FMA2(vh2, phi[nt], phi[nt], vh2);
        }
        float2 vl = unpk(vl2), vh = unpk(vh2);
        float vlo = vl.x + vl.y, vhi = vh.x + vh.y;
        vlo += __shfl_xor_sync(0xffffffffu, vlo, 1);
        vlo += __shfl_xor_sync(0xffffffffu, vlo, 2);
        vhi += __shfl_xor_sync(0xffffffffu, vhi, 1);
        vhi += __shfl_xor_sync(0xffffffffu, vhi, 2);
        float rstdlo = rsqrtf(vlo * (1.0f / 64.0f) + 1e-5f);
        float rstdhi = rsqrtf(vhi * (1.0f / 64.0f) + 1e-5f);
        u64 rl2 = pk2(rstdlo, rstdlo), rh2 = pk2(rstdhi, rstdhi);
        // ---- scale + GELU -------------------------------------------------------
#pragma unroll
        for (int nt = 0; nt < 8; nt++) {
            u64 gm = gmv[nt * 4 + s4], bt = btv[nt * 4 + s4];
            u64 grl; MUL2(grl, gm, rl2);
            u64 grh; MUL2(grh, gm, rh2);
            FMA2(plo[nt], plo[nt], grl, bt);
            FMA2(phi[nt], phi[nt], grh, bt);
            plo[nt] = gelu2(plo[nt]);
            phi[nt] = gelu2(phi[nt]);
        }

        // ---- layer 2: per-k2 A-frag pack + MMA (4-acc round-robin) ------------
        float d2[4][4];
#pragma unroll
        for (int nt = 0; nt < 4; nt++)
#pragma unroll
            for (int j = 0; j < 4; j++) d2[nt][j] = 0.f;

#pragma unroll
        for (int k2 = 0; k2 < 4; k2++) {
            uint32_t A2h[4], A2l[4];
            {
                Split s0 = split2p(plo[2 * k2]);
                Split s1 = split2p(phi[2 * k2]);
                Split s2 = split2p(plo[2 * k2 + 1]);
                Split s3 = split2p(phi[2 * k2 + 1]);
                A2h[0] = s0.hi; A2l[0] = s0.lo;
                A2h[1] = s1.hi; A2l[1] = s1.lo;
                A2h[2] = s2.hi; A2l[2] = s2.lo;
                A2h[3] = s3.hi; A2l[3] = s3.lo;
            }
            const uint2* bp_hi = reinterpret_cast<const uint2*>(
                smu + B2F + ((k2 * 4 + s4) * 36 + q) * 2);
            const uint2* bp_lo = reinterpret_cast<const uint2*>(
                smu + B2F + ((16 + k2 * 4 + s4) * 36 + q) * 2);
            uint2 bh[4], bl[4];
#pragma unroll
            for (int nt = 0; nt < 4; nt++) { bh[nt] = bp_hi[nt * 8]; bl[nt] = bp_lo[nt * 8]; }
#pragma unroll
            for (int nt = 0; nt < 4; nt++) mma_bf16(d2[nt], A2h, bh[nt].x, bh[nt].y);
#pragma unroll
            for (int nt = 0; nt < 4; nt++) mma_bf16(d2[nt], A2h, bl[nt].x, bl[nt].y);
#pragma unroll
            for (int nt = 0; nt < 4; nt++) mma_bf16(d2[nt], A2l, bh[nt].x, bh[nt].y);
        }

        // ---- bias + GELU on layer-2 output --------------------------------------
        u64 qlo[4], qhi[4];
#pragma unroll
        for (int nt = 0; nt < 4; nt++) {
            u64 bp = b2v[nt * 4 + s4];
            u64 a = pk2(d2[nt][0], d2[nt][1]);
            u64 b = pk2(d2[nt][2], d2[nt][3]);
            ADD2(a, a, bp);
            ADD2(b, b, bp);
            qlo[nt] = gelu2(a);
            qhi[nt] = gelu2(b);
        }

        // ---- merged heads: o = heff@Wg + 0.3*(h@Wr[r]) + 0.7bg + 0.3br ---------
        int growlo = warpRow + t * 16 + q;
        int growhi = growlo + 8;
        int rrlo = regime[growlo > Bm1 ? Bm1 : growlo];
        int rrhi = regime[growhi > Bm1 ? Bm1 : growhi];
        const u64* wrlo = reinterpret_cast<const u64*>(par + P_WR + rrlo * 64);
        const u64* wrhi = reinterpret_cast<const u64*>(par + P_WR + rrhi * 64);
        const float* sglo = par + P_SG + rrlo * 36;
        const float* sghi = par + P_SG + rrhi * 36;

        u64 ca2lo = 0ull, cr2lo = 0ull, ca2hi = 0ull, cr2hi = 0ull;
#pragma unroll
        for (int nt = 0; nt < 4; nt++) {
            int ch = nt * 8 + s4 * 2;
            float2 h2  = unpk(qlo[nt]);
            float2 k2v = unpk(qhi[nt]);
            float2 sl = *reinterpret_cast<const float2*>(sglo + ch);
            float2 sh = *reinterpret_cast<const float2*>(sghi + ch);
            float e0 = h2.x * sl.x,  e1 = h2.y * sl.y;     // heff (lo rows)
            float f0 = k2v.x * sh.x, f1 = k2v.y * sh.y;    // heff (hi rows)
            FMA2(ca2lo, pk2(e0, e0), wgv[ch],     ca2lo);
            FMA2(ca2lo, pk2(e1, e1), wgv[ch + 1], ca2lo);
            FMA2(cr2lo, pk2(h2.x, h2.x), wrlo[ch],     cr2lo);
            FMA2(cr2lo, pk2(h2.y, h2.y), wrlo[ch + 1], cr2lo);
            FMA2(ca2hi, pk2(f0, f0), wgv[ch],     ca2hi);
            FMA2(ca2hi, pk2(f1, f1), wgv[ch + 1], ca2hi);
            FMA2(cr2hi, pk2(k2v.x, k2v.x), wrhi[ch],     cr2hi);
            FMA2(cr2hi, pk2(k2v.y, k2v.y), wrhi[ch + 1], cr2hi);
        }
        float2 calo = unpk(ca2lo), crlo = unpk(cr2lo);
        float2 cahi = unpk(ca2hi), crhi = unpk(cr2hi);
#pragma unroll
        for (int d = 1; d <= 2; d <<= 1) {
            calo.x += __shfl_xor_sync(0xffffffffu, calo.x, d);
            calo.y += __shfl_xor_sync(0xffffffffu, calo.y, d);
            crlo.x += __shfl_xor_sync(0xffffffffu, crlo.x, d);
            crlo.y += __shfl_xor_sync(0xffffffffu, crlo.y, d);
            cahi.x += __shfl_xor_sync(0xffffffffu, cahi.x, d);
            cahi.y += __shfl_xor_sync(0xffffffffu, cahi.y, d);
            crhi.x += __shfl_xor_sync(0xffffffffu, crhi.x, d);
            crhi.y += __shfl_xor_sync(0xffffffffu, crhi.y, d);
        }

        if (s4 == 0) {
            const float bg0 = par[P_BG], bg1 = par[P_BG + 1];
            if (growlo < B) {
                float2 o;
                o.x = (calo.x + 0.3f * crlo.x + bg0 + par[P_BR + rrlo * 2]) * it;
                o.y = (calo.y + 0.3f * crlo.y + bg1 + par[P_BR + rrlo * 2 + 1]) * it;
                reinterpret_cast<float2*>(out)[growlo] = o;
            }
            if (growhi < B) {
                float2 o;
                o.x = (cahi.x + 0.3f * crhi.x + bg0 + par[P_BR + rrhi * 2]) * it;
                o.y = (cahi.y + 0.3f * crhi.y + bg1 + par[P_BR + rrhi * 2 + 1]) * it;
                reinterpret_cast<float2*>(out)[growhi] = o;
            }
        }
    }
}

extern "C" void kernel_launch(void* const* d_in, const int* in_sizes, int n_in,
                              void* d_out, int out_size)
{
    const float* x        = (const float*)d_in[0];
    const int*   regime   = (const int*)  d_in[1];
    const float* W1       = (const float*)d_in[2];
    const float* b1       = (const float*)d_in[3];
    const float* gamma    = (const float*)d_in[4];
    const float* beta     = (const float*)d_in[5];
    const float* W2       = (const float*)d_in[6];
    const float* b2       = (const float*)d_in[7];
    const float* Wg       = (const float*)d_in[8];
    const float* bg       = (const float*)d_in[9];
    const float* Wr       = (const float*)d_in[10];
    const float* br       = (const float*)d_in[11];
    const float* emb      = (const float*)d_in[12];
    const float* log_temp = (const float*)d_in[13];
    float* out = (float*)d_out;

    const int B = in_sizes[1];
    const int grid = (B + ROWS - 1) / ROWS;

    cudaFuncSetAttribute(nml_mma_kernel,
                         cudaFuncAttributeMaxDynamicSharedMemorySize, SMEM_BYTES);
    nml_mma_kernel<<<grid, TPB, SMEM_BYTES>>>(x, regime, W1, b1, gamma, beta,
                                              W2, b2, Wg, bg, Wr, br, emb,
                                              log_temp, out, B);
}